// round 6
// baseline (speedup 1.0000x reference)
#include <cuda_runtime.h>
#include <cstdint>

#define N_NODES 50000
#define D 128
#define R_REL 8
#define E_EDGES 800000
#define NR (N_NODES * R_REL)   // 400000
#define KTOT 1152              // R*D + D
#define KA 1024                // R*D

#define SCAN_BLK 4096
#define NSCAN ((NR + SCAN_BLK - 1) / SCAN_BLK)   // 98

// Scratch (__device__ globals; no allocation allowed)
__device__ float g_A[(size_t)N_NODES * KTOT];    // [N,1152] tf32-rounded A matrix
__device__ float g_B[KTOT * 128];                // [1152,128] tf32-rounded weights
__device__ int g_cnt[NR];
__device__ int g_cur[NR];
__device__ int g_off[NR];
__device__ int g_bsum[NSCAN + 1];
__device__ int g_eidx[E_EDGES];

__device__ __forceinline__ uint32_t f2tf(float f) {
    uint32_t u;
    asm("cvt.rna.tf32.f32 %0, %1;" : "=r"(u) : "f"(f));
    return u;
}
__device__ __forceinline__ uint32_t smem_u32(const void* p) {
    uint32_t a;
    asm("{ .reg .u64 t; cvta.to.shared.u64 t, %1; cvt.u32.u64 %0, t; }" : "=r"(a) : "l"(p));
    return a;
}
__device__ __forceinline__ void cp16(uint32_t dst, const void* src, int sz) {
    asm volatile("cp.async.cg.shared.global [%0], [%1], 16, %2;"
                 :: "r"(dst), "l"(src), "r"(sz) : "memory");
}

// ---------------------------------------------------------------------------
// Counters / histogram / scan / fill (CSR build)
// ---------------------------------------------------------------------------
__global__ void zero_cnt_kernel() {
    const int i = blockIdx.x * blockDim.x + threadIdx.x;
    if (i < NR) { g_cnt[i] = 0; g_cur[i] = 0; }
}

__global__ void hist_kernel(const int* __restrict__ nout, const int* __restrict__ rel) {
    const int e = blockIdx.x * blockDim.x + threadIdx.x;
    if (e < E_EDGES) atomicAdd(&g_cnt[nout[e] * R_REL + rel[e]], 1);
}

__global__ void scan1_kernel() {
    __shared__ int sd[256];
    const int t = threadIdx.x;
    const int base = blockIdx.x * SCAN_BLK + t * 16;
    int v[16], sum = 0;
    #pragma unroll
    for (int j = 0; j < 16; j++) {
        v[j] = sum;
        const int idx = base + j;
        sum += (idx < NR) ? g_cnt[idx] : 0;
    }
    sd[t] = sum;
    __syncthreads();
    #pragma unroll
    for (int d = 1; d < 256; d <<= 1) {
        int val = sd[t];
        if (t >= d) val += sd[t - d];
        __syncthreads();
        sd[t] = val;
        __syncthreads();
    }
    const int excl = sd[t] - sum;
    #pragma unroll
    for (int j = 0; j < 16; j++) {
        const int idx = base + j;
        if (idx < NR) g_off[idx] = excl + v[j];
    }
    if (t == 255) g_bsum[blockIdx.x] = sd[255];
}

__global__ void scan2_kernel() {
    __shared__ int sd[128];
    const int t = threadIdx.x;
    const int orig = (t < NSCAN) ? g_bsum[t] : 0;
    sd[t] = orig;
    __syncthreads();
    #pragma unroll
    for (int d = 1; d < 128; d <<= 1) {
        int val = sd[t];
        if (t >= d) val += sd[t - d];
        __syncthreads();
        sd[t] = val;
        __syncthreads();
    }
    if (t < NSCAN) g_bsum[t] = sd[t] - orig;
}

__global__ void scan3_kernel() {
    const int i = blockIdx.x * blockDim.x + threadIdx.x;
    if (i < NR) g_off[i] += g_bsum[i / SCAN_BLK];
}

__global__ void fill_kernel(const int* __restrict__ nout, const int* __restrict__ rel) {
    const int e = blockIdx.x * blockDim.x + threadIdx.x;
    if (e >= E_EDGES) return;
    const int seg = nout[e] * R_REL + rel[e];
    const int pos = g_off[seg] + atomicAdd(&g_cur[seg], 1);
    g_eidx[pos] = e;
}

// ---------------------------------------------------------------------------
// Prep: tf32-rounded weights into g_B, tf32-rounded x into g_A[:,1024:]
// ---------------------------------------------------------------------------
__global__ void prep_w_kernel(const float* __restrict__ Wlin, const float* __restrict__ Wloop) {
    const int idx = blockIdx.x * blockDim.x + threadIdx.x;
    if (idx >= KTOT * 128) return;
    const int k = idx >> 7;
    const int n = idx & 127;
    const float v = (k < KA) ? Wlin[(size_t)k * 128 + n] : Wloop[(size_t)(k - KA) * 128 + n];
    g_B[idx] = __uint_as_float(f2tf(v));
}

__global__ void prep_x_kernel(const float* __restrict__ x) {
    const int idx = blockIdx.x * blockDim.x + threadIdx.x;
    if (idx >= N_NODES * 128) return;
    const int row = idx >> 7;
    const int col = idx & 127;
    g_A[(size_t)row * KTOT + KA + col] = __uint_as_float(f2tf(x[idx]));
}

// ---------------------------------------------------------------------------
// Aggregate: warp per segment, no atomics; writes tf32-rounded mean into g_A
// ---------------------------------------------------------------------------
__global__ void aggregate_kernel(const float* __restrict__ x,
                                 const float* __restrict__ ew,
                                 const int* __restrict__ nin) {
    const int seg = (blockIdx.x * blockDim.x + threadIdx.x) >> 5;
    const int lane = threadIdx.x & 31;
    if (seg >= NR) return;

    const int start = g_off[seg];
    const int cnt = g_cnt[seg];

    float4 acc = make_float4(0.f, 0.f, 0.f, 0.f);
    float den = 0.f;
    int i = 0;
    for (; i + 2 <= cnt; i += 2) {
        const int e0 = g_eidx[start + i];
        const int e1 = g_eidx[start + i + 1];
        const float w0 = ew[e0], w1 = ew[e1];
        const int v0 = nin[e0], v1 = nin[e1];
        const float4 x0 = *reinterpret_cast<const float4*>(x + (size_t)v0 * D + lane * 4);
        const float4 x1 = *reinterpret_cast<const float4*>(x + (size_t)v1 * D + lane * 4);
        acc.x += w0 * x0.x + w1 * x1.x;
        acc.y += w0 * x0.y + w1 * x1.y;
        acc.z += w0 * x0.z + w1 * x1.z;
        acc.w += w0 * x0.w + w1 * x1.w;
        den += w0 + w1;
    }
    if (i < cnt) {
        const int e0 = g_eidx[start + i];
        const float w0 = ew[e0];
        const int v0 = nin[e0];
        const float4 x0 = *reinterpret_cast<const float4*>(x + (size_t)v0 * D + lane * 4);
        acc.x += w0 * x0.x; acc.y += w0 * x0.y;
        acc.z += w0 * x0.z; acc.w += w0 * x0.w;
        den += w0;
    }
    const float s = 1.0f / (den + 1e-10f);
    // g_A layout: node-row stride KTOT; segment (node,r) occupies cols r*128..
    const int node = seg >> 3;
    const int r = seg & 7;
    uint4 o;
    o.x = f2tf(acc.x * s);
    o.y = f2tf(acc.y * s);
    o.z = f2tf(acc.z * s);
    o.w = f2tf(acc.w * s);
    *reinterpret_cast<uint4*>(g_A + (size_t)node * KTOT + r * 128 + lane * 4) = o;
}

// ---------------------------------------------------------------------------
// TF32 GEMM with cp.async 4-stage pipeline:
// out = relu( g_A @ g_B + b_lin + b_loop ),  g_A/g_B pre-rounded to tf32.
// BM=BN=128, BK=16, 256 threads (2x4 warps, 64x32 warp tiles), m16n8k8.
// ---------------------------------------------------------------------------
#define AS_STRIDE 20      // words per A row (128 rows)
#define BS_STRIDE 136     // words per B k-row (16 k-rows)
#define A_STG_W  (128 * AS_STRIDE)   // 2560 words / stage
#define B_STG_W  (16 * BS_STRIDE)    // 2176 words / stage
#define NSTG 4
#define AS_OFF 0
#define BS_OFF (NSTG * A_STG_W * 4)            // 40960 B
#define BIAS_OFF (BS_OFF + NSTG * B_STG_W * 4) // 75776 B
#define SM_TOTAL (BIAS_OFF + 512)

__global__ __launch_bounds__(256, 2)
void gemm_tf32(const float* __restrict__ blin, const float* __restrict__ bloop,
               float* __restrict__ out) {
    extern __shared__ char smem[];
    uint32_t* sAs = reinterpret_cast<uint32_t*>(smem + AS_OFF);
    uint32_t* sBs = reinterpret_cast<uint32_t*>(smem + BS_OFF);
    float* bias_s = reinterpret_cast<float*>(smem + BIAS_OFF);
    const uint32_t smb = smem_u32(smem);

    const int tid  = threadIdx.x;
    const int n0blk = blockIdx.x * 128;

    if (tid < 128) bias_s[tid] = blin[tid] + bloop[tid];

    const int lane = tid & 31;
    const int wid  = tid >> 5;
    const int g = lane >> 2;
    const int t = lane & 3;
    const int wm = wid >> 2;
    const int wn = wid & 3;

    // cp.async chunk mapping: thread handles A chunks {2tid, 2tid+1}, B same.
    // A chunk c (0..511): row=c>>2, kq=(c&3)*4.   B chunk c: k=c>>5, n=(c&31)*4.
    const int ar0 = (tid * 2) >> 2;            // A row of first chunk
    const int ak0 = ((tid * 2) & 3) * 4;       // its k-offset
    const int ar1 = (tid * 2 + 1) >> 2;
    const int ak1 = ((tid * 2 + 1) & 3) * 4;
    const int bk0 = (tid * 2) >> 5;
    const int bn0 = ((tid * 2) & 31) * 4;
    const int bk1 = (tid * 2 + 1) >> 5;
    const int bn1 = ((tid * 2 + 1) & 31) * 4;
    const int asz0 = (n0blk + ar0 < N_NODES) ? 16 : 0;
    const int asz1 = (n0blk + ar1 < N_NODES) ? 16 : 0;
    const size_t arow0_off = (size_t)min(n0blk + ar0, N_NODES - 1) * KTOT;
    const size_t arow1_off = (size_t)min(n0blk + ar1, N_NODES - 1) * KTOT;

#define ISSUE(ST, K0) do {                                                       \
    const uint32_t ab = smb + AS_OFF + (ST) * (A_STG_W * 4);                     \
    const uint32_t bb = smb + BS_OFF + (ST) * (B_STG_W * 4);                     \
    cp16(ab + (ar0 * AS_STRIDE + ak0) * 4, g_A + arow0_off + (K0) + ak0, asz0);  \
    cp16(ab + (ar1 * AS_STRIDE + ak1) * 4, g_A + arow1_off + (K0) + ak1, asz1);  \
    cp16(bb + (bk0 * BS_STRIDE + bn0) * 4, g_B + ((K0) + bk0) * 128 + bn0, 16);  \
    cp16(bb + (bk1 * BS_STRIDE + bn1) * 4, g_B + ((K0) + bk1) * 128 + bn1, 16);  \
    asm volatile("cp.async.commit_group;" ::: "memory");                         \
} while (0)

#define MMA(CC, A0, A1, A2, A3, B0, B1)                                          \
    asm volatile(                                                                \
        "mma.sync.aligned.m16n8k8.row.col.f32.tf32.tf32.f32 "                    \
        "{%0,%1,%2,%3}, {%4,%5,%6,%7}, {%8,%9}, {%0,%1,%2,%3};\n"                \
        : "+f"(CC[0]), "+f"(CC[1]), "+f"(CC[2]), "+f"(CC[3])                     \
        : "r"(A0), "r"(A1), "r"(A2), "r"(A3), "r"(B0), "r"(B1))

#define COMPUTE_STAGE(ST) do {                                                   \
    const uint32_t* As_ = sAs + (ST) * A_STG_W;                                  \
    const uint32_t* Bs_ = sBs + (ST) * B_STG_W;                                  \
    _Pragma("unroll")                                                            \
    for (int s = 0; s < 2; s++) {                                                \
        const int kk = s * 8;                                                    \
        uint32_t a[4][4], b[4][2];                                               \
        _Pragma("unroll")                                                        \
        for (int mt = 0; mt < 4; mt++) {                                         \
            const int r = wm * 64 + mt * 16 + g;                                 \
            a[mt][0] = As_[r * AS_STRIDE + kk + t];                              \
            a[mt][1] = As_[(r + 8) * AS_STRIDE + kk + t];                        \
            a[mt][2] = As_[r * AS_STRIDE + kk + t + 4];                          \
            a[mt][3] = As_[(r + 8) * AS_STRIDE + kk + t + 4];                    \
        }                                                                        \
        _Pragma("unroll")                                                        \
        for (int nt = 0; nt < 4; nt++) {                                         \
            const int cn = wn * 32 + nt * 8 + g;                                 \
            b[nt][0] = Bs_[(kk + t) * BS_STRIDE + cn];                           \
            b[nt][1] = Bs_[(kk + t + 4) * BS_STRIDE + cn];                       \
        }                                                                        \
        _Pragma("unroll")                                                        \
        for (int mt = 0; mt < 4; mt++)                                           \
            _Pragma("unroll")                                                    \
            for (int nt = 0; nt < 4; nt++)                                       \
                MMA(c[mt][nt], a[mt][0], a[mt][1], a[mt][2], a[mt][3],           \
                    b[nt][0], b[nt][1]);                                         \
    }                                                                            \
} while (0)

    float c[4][4][4];
    #pragma unroll
    for (int mt = 0; mt < 4; mt++)
        #pragma unroll
        for (int nt = 0; nt < 4; nt++)
            #pragma unroll
            for (int q = 0; q < 4; q++) c[mt][nt][q] = 0.f;

    const int NIT = KTOT / 16;   // 72

    ISSUE(0, 0);
    ISSUE(1, 16);
    ISSUE(2, 32);

    for (int it = 0; it < NIT; it++) {
        const int st = it & (NSTG - 1);
        const int rem = NIT - 1 - it;
        if (rem >= 2)      asm volatile("cp.async.wait_group 2;" ::: "memory");
        else if (rem == 1) asm volatile("cp.async.wait_group 1;" ::: "memory");
        else               asm volatile("cp.async.wait_group 0;" ::: "memory");
        __syncthreads();
        if (it + 3 < NIT) ISSUE((it + 3) & (NSTG - 1), (it + 3) * 16);
        COMPUTE_STAGE(st);
    }

    // Epilogue: bias + relu + store
    #pragma unroll
    for (int mt = 0; mt < 4; mt++) {
        const int r0 = n0blk + wm * 64 + mt * 16 + g;
        const int r1 = r0 + 8;
        #pragma unroll
        for (int nt = 0; nt < 4; nt++) {
            const int cn = wn * 32 + nt * 8 + 2 * t;
            const float b0 = bias_s[cn], b1 = bias_s[cn + 1];
            if (r0 < N_NODES) {
                float2 v;
                v.x = fmaxf(c[mt][nt][0] + b0, 0.f);
                v.y = fmaxf(c[mt][nt][1] + b1, 0.f);
                *reinterpret_cast<float2*>(out + (size_t)r0 * 128 + cn) = v;
            }
            if (r1 < N_NODES) {
                float2 v;
                v.x = fmaxf(c[mt][nt][2] + b0, 0.f);
                v.y = fmaxf(c[mt][nt][3] + b1, 0.f);
                *reinterpret_cast<float2*>(out + (size_t)r1 * 128 + cn) = v;
            }
        }
    }
}

// ---------------------------------------------------------------------------
// Launch. Inputs: 0:x 1:edge_weight 2:W_lin 3:b_lin 4:W_loop 5:b_loop
//                 6:node_in 7:node_out 8:relation
// ---------------------------------------------------------------------------
extern "C" void kernel_launch(void* const* d_in, const int* in_sizes, int n_in,
                              void* d_out, int out_size) {
    const float* x     = (const float*)d_in[0];
    const float* ew    = (const float*)d_in[1];
    const float* Wlin  = (const float*)d_in[2];
    const float* blin  = (const float*)d_in[3];
    const float* Wloop = (const float*)d_in[4];
    const float* bloop = (const float*)d_in[5];
    const int* nin     = (const int*)d_in[6];
    const int* nout    = (const int*)d_in[7];
    const int* rel     = (const int*)d_in[8];
    float* out         = (float*)d_out;

    cudaFuncSetAttribute(gemm_tf32, cudaFuncAttributeMaxDynamicSharedMemorySize, SM_TOTAL);

    zero_cnt_kernel<<<(NR + 255) / 256, 256>>>();
    hist_kernel<<<(E_EDGES + 255) / 256, 256>>>(nout, rel);
    prep_w_kernel<<<(KTOT * 128 + 255) / 256, 256>>>(Wlin, Wloop);
    prep_x_kernel<<<(N_NODES * 128 + 255) / 256, 256>>>(x);
    scan1_kernel<<<NSCAN, 256>>>();
    scan2_kernel<<<1, 128>>>();
    scan3_kernel<<<(NR + 255) / 256, 256>>>();
    fill_kernel<<<(E_EDGES + 255) / 256, 256>>>(nout, rel);
    aggregate_kernel<<<NR / 8, 256>>>(x, ew, nin);
    gemm_tf32<<<(N_NODES + 127) / 128, 256, SM_TOTAL>>>(blin, bloop, out);
}

// round 9
// speedup vs baseline: 1.0199x; 1.0199x over previous
#include <cuda_runtime.h>
#include <cstdint>

#define N_NODES 50000
#define D 128
#define R_REL 8
#define E_EDGES 800000
#define NR (N_NODES * R_REL)   // 400000
#define KTOT 1152              // R*D + D
#define KA 1024                // R*D

#define SCAN_BLK 4096
#define NSCAN ((NR + SCAN_BLK - 1) / SCAN_BLK)   // 98

// Scratch (__device__ globals; no allocation allowed)
__device__ float g_A[(size_t)N_NODES * KTOT];    // [N,1152] tf32-rounded A
__device__ float g_BT[128 * KTOT];               // [n=128, k=1152] tf32-rounded W^T
__device__ int g_cnt[NR];
__device__ int g_cur[NR];
__device__ int g_off[NR];
__device__ int g_bsum[NSCAN + 1];
__device__ int g_eidx[E_EDGES];

__device__ __forceinline__ uint32_t f2tf(float f) {
    uint32_t u;
    asm("cvt.rna.tf32.f32 %0, %1;" : "=r"(u) : "f"(f));
    return u;
}
__device__ __forceinline__ uint32_t smem_u32(const void* p) {
    uint32_t a;
    asm("{ .reg .u64 t; cvta.to.shared.u64 t, %1; cvt.u32.u64 %0, t; }" : "=r"(a) : "l"(p));
    return a;
}
__device__ __forceinline__ void cp16(uint32_t dst, const void* src, int sz) {
    asm volatile("cp.async.cg.shared.global [%0], [%1], 16, %2;"
                 :: "r"(dst), "l"(src), "r"(sz) : "memory");
}

// ---------------------------------------------------------------------------
// CSR build: zero counters, histogram, scan, fill
// ---------------------------------------------------------------------------
__global__ void zero_cnt_kernel() {
    const int i = blockIdx.x * blockDim.x + threadIdx.x;
    if (i < NR) { g_cnt[i] = 0; g_cur[i] = 0; }
}

__global__ void hist_kernel(const int* __restrict__ nout, const int* __restrict__ rel) {
    const int e = blockIdx.x * blockDim.x + threadIdx.x;
    if (e < E_EDGES) atomicAdd(&g_cnt[nout[e] * R_REL + rel[e]], 1);
}

__global__ void scan1_kernel() {
    __shared__ int sd[256];
    const int t = threadIdx.x;
    const int base = blockIdx.x * SCAN_BLK + t * 16;
    int v[16], sum = 0;
    #pragma unroll
    for (int j = 0; j < 16; j++) {
        v[j] = sum;
        const int idx = base + j;
        sum += (idx < NR) ? g_cnt[idx] : 0;
    }
    sd[t] = sum;
    __syncthreads();
    #pragma unroll
    for (int d = 1; d < 256; d <<= 1) {
        int val = sd[t];
        if (t >= d) val += sd[t - d];
        __syncthreads();
        sd[t] = val;
        __syncthreads();
    }
    const int excl = sd[t] - sum;
    #pragma unroll
    for (int j = 0; j < 16; j++) {
        const int idx = base + j;
        if (idx < NR) g_off[idx] = excl + v[j];
    }
    if (t == 255) g_bsum[blockIdx.x] = sd[255];
}

__global__ void scan2_kernel() {
    __shared__ int sd[128];
    const int t = threadIdx.x;
    const int orig = (t < NSCAN) ? g_bsum[t] : 0;
    sd[t] = orig;
    __syncthreads();
    #pragma unroll
    for (int d = 1; d < 128; d <<= 1) {
        int val = sd[t];
        if (t >= d) val += sd[t - d];
        __syncthreads();
        sd[t] = val;
        __syncthreads();
    }
    if (t < NSCAN) g_bsum[t] = sd[t] - orig;
}

__global__ void scan3_kernel() {
    const int i = blockIdx.x * blockDim.x + threadIdx.x;
    if (i < NR) g_off[i] += g_bsum[i / SCAN_BLK];
}

__global__ void fill_kernel(const int* __restrict__ nout, const int* __restrict__ rel) {
    const int e = blockIdx.x * blockDim.x + threadIdx.x;
    if (e >= E_EDGES) return;
    const int seg = nout[e] * R_REL + rel[e];
    const int pos = g_off[seg] + atomicAdd(&g_cur[seg], 1);
    g_eidx[pos] = e;
}

// ---------------------------------------------------------------------------
// Prep: tf32-rounded TRANSPOSED weights into g_BT[n][k]
// ---------------------------------------------------------------------------
__global__ void prep_w_kernel(const float* __restrict__ Wlin, const float* __restrict__ Wloop) {
    const int idx = blockIdx.x * blockDim.x + threadIdx.x;
    if (idx >= 128 * KTOT) return;
    const int n = idx / KTOT;
    const int k = idx % KTOT;
    const float v = (k < KA) ? Wlin[(size_t)k * 128 + n] : Wloop[(size_t)(k - KA) * 128 + n];
    g_BT[idx] = __uint_as_float(f2tf(v));
}

// ---------------------------------------------------------------------------
// Aggregate: warp per segment; also copies tf32-rounded x row (r==0 warp)
// ---------------------------------------------------------------------------
__global__ void aggregate_kernel(const float* __restrict__ x,
                                 const float* __restrict__ ew,
                                 const int* __restrict__ nin) {
    const int seg = (blockIdx.x * blockDim.x + threadIdx.x) >> 5;
    const int lane = threadIdx.x & 31;
    if (seg >= NR) return;

    const int node = seg >> 3;
    const int r = seg & 7;

    if (r == 0) {   // copy x row into g_A cols 1024..1151 (tf32-rounded)
        const float4 xv = *reinterpret_cast<const float4*>(x + (size_t)node * D + lane * 4);
        uint4 o;
        o.x = f2tf(xv.x); o.y = f2tf(xv.y); o.z = f2tf(xv.z); o.w = f2tf(xv.w);
        *reinterpret_cast<uint4*>(g_A + (size_t)node * KTOT + KA + lane * 4) = o;
    }

    const int start = g_off[seg];
    const int cnt = g_cnt[seg];

    float4 acc = make_float4(0.f, 0.f, 0.f, 0.f);
    float den = 0.f;
    int i = 0;
    for (; i + 2 <= cnt; i += 2) {
        const int e0 = g_eidx[start + i];
        const int e1 = g_eidx[start + i + 1];
        const float w0 = ew[e0], w1 = ew[e1];
        const int v0 = nin[e0], v1 = nin[e1];
        const float4 x0 = *reinterpret_cast<const float4*>(x + (size_t)v0 * D + lane * 4);
        const float4 x1 = *reinterpret_cast<const float4*>(x + (size_t)v1 * D + lane * 4);
        acc.x += w0 * x0.x + w1 * x1.x;
        acc.y += w0 * x0.y + w1 * x1.y;
        acc.z += w0 * x0.z + w1 * x1.z;
        acc.w += w0 * x0.w + w1 * x1.w;
        den += w0 + w1;
    }
    if (i < cnt) {
        const int e0 = g_eidx[start + i];
        const float w0 = ew[e0];
        const int v0 = nin[e0];
        const float4 x0 = *reinterpret_cast<const float4*>(x + (size_t)v0 * D + lane * 4);
        acc.x += w0 * x0.x; acc.y += w0 * x0.y;
        acc.z += w0 * x0.z; acc.w += w0 * x0.w;
        den += w0;
    }
    const float s = 1.0f / (den + 1e-10f);
    uint4 o;
    o.x = f2tf(acc.x * s);
    o.y = f2tf(acc.y * s);
    o.z = f2tf(acc.z * s);
    o.w = f2tf(acc.w * s);
    *reinterpret_cast<uint4*>(g_A + (size_t)node * KTOT + r * 128 + lane * 4) = o;
}

// ---------------------------------------------------------------------------
// TF32 GEMM: cp.async 4-stage pipeline + ldmatrix fragment loads.
// out = relu( g_A @ g_BT^T + bias ).  Both tiles stored [row][k], stride 20 w.
// BM=BN=128, BK=16, 256 threads (2x4 warps, 64x32 warp tiles), m16n8k8.
// ---------------------------------------------------------------------------
#define TS 20                          // words per tile row (16 k + 4 pad)
#define STG_W (128 * TS)               // 2560 words / stage / operand
#define STG_B (STG_W * 4)              // 10240 B
#define NSTG 4
#define AS_OFF 0
#define BS_OFF (NSTG * STG_B)          // 40960
#define BIAS_OFF (2 * NSTG * STG_B)    // 81920
#define SM_TOTAL (BIAS_OFF + 512)

#define LDSM4(R0, R1, R2, R3, ADDR)                                             \
    asm volatile("ldmatrix.sync.aligned.m8n8.x4.shared.b16 {%0,%1,%2,%3}, [%4];"\
                 : "=r"(R0), "=r"(R1), "=r"(R2), "=r"(R3) : "r"(ADDR))
#define LDSM2(R0, R1, ADDR)                                                     \
    asm volatile("ldmatrix.sync.aligned.m8n8.x2.shared.b16 {%0,%1}, [%2];"      \
                 : "=r"(R0), "=r"(R1) : "r"(ADDR))

__global__ __launch_bounds__(256, 2)
void gemm_tf32(const float* __restrict__ blin, const float* __restrict__ bloop,
               float* __restrict__ out) {
    extern __shared__ char smem[];
    float* bias_s = reinterpret_cast<float*>(smem + BIAS_OFF);
    const uint32_t smb = smem_u32(smem);

    const int tid  = threadIdx.x;
    const int n0blk = blockIdx.x * 128;

    if (tid < 128) bias_s[tid] = blin[tid] + bloop[tid];

    const int lane = tid & 31;
    const int wid  = tid >> 5;
    const int g = lane >> 2;
    const int t = lane & 3;
    const int wm = wid >> 2;     // 0..1, 64 rows
    const int wn = wid & 3;      // 0..3, 32 cols

    // cp.async chunk mapping (identical for A and B): 128 rows x 4 chunks of 16B.
    const int r0c = (tid * 2) >> 2;            // row of chunk pair
    const int kc0 = ((tid * 2) & 3) * 4;       // k-offset of chunk 0
    const int kc1 = kc0 + 4;                   // chunk 1 (same row)
    const int asz = (n0blk + r0c < N_NODES) ? 16 : 0;
    const size_t arow_off = (size_t)min(n0blk + r0c, N_NODES - 1) * KTOT;
    const size_t brow_off = (size_t)r0c * KTOT;

    // ldmatrix per-lane address offsets (words within a stage tile)
    const int lm_row = (lane & 7) + ((lane >> 3) & 1) * 8;   // x4 row mapping
    const int lm_c4  = ((lane >> 4) & 1) * 4;                // x4 col +4 for mats 2,3
    const int a_off  = ((wm * 64 + lm_row) * TS + lm_c4) * 4;    // bytes
    const int lb     = lane & 15;
    const int b_off  = ((wn * 32 + (lb & 7)) * TS + ((lb >> 3) & 1) * 4) * 4;

#define ISSUE(ST, K0) do {                                                       \
    const uint32_t ab = smb + AS_OFF + (ST) * STG_B;                             \
    const uint32_t bb = smb + BS_OFF + (ST) * STG_B;                             \
    cp16(ab + (r0c * TS + kc0) * 4, g_A + arow_off + (K0) + kc0, asz);           \
    cp16(ab + (r0c * TS + kc1) * 4, g_A + arow_off + (K0) + kc1, asz);           \
    cp16(bb + (r0c * TS + kc0) * 4, g_BT + brow_off + (K0) + kc0, 16);           \
    cp16(bb + (r0c * TS + kc1) * 4, g_BT + brow_off + (K0) + kc1, 16);           \
    asm volatile("cp.async.commit_group;" ::: "memory");                         \
} while (0)

#define MMA(CC, A0, A1, A2, A3, B0, B1)                                          \
    asm volatile(                                                                \
        "mma.sync.aligned.m16n8k8.row.col.f32.tf32.tf32.f32 "                    \
        "{%0,%1,%2,%3}, {%4,%5,%6,%7}, {%8,%9}, {%0,%1,%2,%3};\n"                \
        : "+f"(CC[0]), "+f"(CC[1]), "+f"(CC[2]), "+f"(CC[3])                     \
        : "r"(A0), "r"(A1), "r"(A2), "r"(A3), "r"(B0), "r"(B1))

#define COMPUTE_STAGE(ST) do {                                                   \
    const uint32_t ab = smb + AS_OFF + (ST) * STG_B + a_off;                     \
    const uint32_t bb = smb + BS_OFF + (ST) * STG_B + b_off;                     \
    _Pragma("unroll")                                                            \
    for (int s = 0; s < 2; s++) {                                                \
        uint32_t a[4][4], b[4][2];                                               \
        _Pragma("unroll")                                                        \
        for (int mt = 0; mt < 4; mt++)                                           \
            LDSM4(a[mt][0], a[mt][1], a[mt][2], a[mt][3],                        \
                  ab + (mt * 16 * TS + s * 8) * 4);                              \
        _Pragma("unroll")                                                        \
        for (int nt = 0; nt < 4; nt++)                                           \
            LDSM2(b[nt][0], b[nt][1], bb + (nt * 8 * TS + s * 8) * 4);           \
        _Pragma("unroll")                                                        \
        for (int mt = 0; mt < 4; mt++)                                           \
            _Pragma("unroll")                                                    \
            for (int nt = 0; nt < 4; nt++)                                       \
                MMA(c[mt][nt], a[mt][0], a[mt][1], a[mt][2], a[mt][3],           \
                    b[nt][0], b[nt][1]);                                         \
    }                                                                            \
} while (0)

    float c[4][4][4];
    #pragma unroll
    for (int mt = 0; mt < 4; mt++)
        #pragma unroll
        for (int nt = 0; nt < 4; nt++)
            #pragma unroll
            for (int q = 0; q < 4; q++) c[mt][nt][q] = 0.f;

    const int NIT = KTOT / 16;   // 72

    ISSUE(0, 0);
    ISSUE(1, 16);
    ISSUE(2, 32);

    for (int it = 0; it < NIT; it++) {
        const int st = it & (NSTG - 1);
        const int rem = NIT - 1 - it;
        if (rem >= 2)      asm volatile("cp.async.wait_group 2;" ::: "memory");
        else if (rem == 1) asm volatile("cp.async.wait_group 1;" ::: "memory");
        else               asm volatile("cp.async.wait_group 0;" ::: "memory");
        __syncthreads();
        if (it + 3 < NIT) ISSUE((it + 3) & (NSTG - 1), (it + 3) * 16);
        COMPUTE_STAGE(st);
    }

    // Epilogue: bias + relu + store
    #pragma unroll
    for (int mt = 0; mt < 4; mt++) {
        const int r0 = n0blk + wm * 64 + mt * 16 + g;
        const int r1 = r0 + 8;
        #pragma unroll
        for (int nt = 0; nt < 4; nt++) {
            const int cn = wn * 32 + nt * 8 + 2 * t;
            const float b0 = bias_s[cn], b1 = bias_s[cn + 1];
            if (r0 < N_NODES) {
                float2 v;
                v.x = fmaxf(c[mt][nt][0] + b0, 0.f);
                v.y = fmaxf(c[mt][nt][1] + b1, 0.f);
                *reinterpret_cast<float2*>(out + (size_t)r0 * 128 + cn) = v;
            }
            if (r1 < N_NODES) {
                float2 v;
                v.x = fmaxf(c[mt][nt][2] + b0, 0.f);
                v.y = fmaxf(c[mt][nt][3] + b1, 0.f);
                *reinterpret_cast<float2*>(out + (size_t)r1 * 128 + cn) = v;
            }
        }
    }
}

// ---------------------------------------------------------------------------
// Launch. Inputs: 0:x 1:edge_weight 2:W_lin 3:b_lin 4:W_loop 5:b_loop
//                 6:node_in 7:node_out 8:relation
// ---------------------------------------------------------------------------
extern "C" void kernel_launch(void* const* d_in, const int* in_sizes, int n_in,
                              void* d_out, int out_size) {
    const float* x     = (const float*)d_in[0];
    const float* ew    = (const float*)d_in[1];
    const float* Wlin  = (const float*)d_in[2];
    const float* blin  = (const float*)d_in[3];
    const float* Wloop = (const float*)d_in[4];
    const float* bloop = (const float*)d_in[5];
    const int* nin     = (const int*)d_in[6];
    const int* nout    = (const int*)d_in[7];
    const int* rel     = (const int*)d_in[8];
    float* out         = (float*)d_out;

    cudaFuncSetAttribute(gemm_tf32, cudaFuncAttributeMaxDynamicSharedMemorySize, SM_TOTAL);

    zero_cnt_kernel<<<(NR + 255) / 256, 256>>>();
    hist_kernel<<<(E_EDGES + 255) / 256, 256>>>(nout, rel);
    prep_w_kernel<<<(128 * KTOT + 255) / 256, 256>>>(Wlin, Wloop);
    scan1_kernel<<<NSCAN, 256>>>();
    scan2_kernel<<<1, 128>>>();
    scan3_kernel<<<(NR + 255) / 256, 256>>>();
    fill_kernel<<<(E_EDGES + 255) / 256, 256>>>(nout, rel);
    aggregate_kernel<<<NR / 8, 256>>>(x, ew, nin);
    gemm_tf32<<<(N_NODES + 127) / 128, 256, SM_TOTAL>>>(blin, bloop, out);
}

// round 12
// speedup vs baseline: 1.3750x; 1.3482x over previous
#include <cuda_runtime.h>
#include <cuda_fp16.h>
#include <cstdint>

#define N_NODES 50000
#define D 128
#define R_REL 8
#define E_EDGES 800000
#define NR (N_NODES * R_REL)   // 400000
#define KTOT 1152              // R*D + D
#define KA 1024                // R*D
#define NTILES 391             // M tiles of 128

#define SCAN_BLK 4096
#define NSCAN ((NR + SCAN_BLK - 1) / SCAN_BLK)   // 98

// Scratch (__device__ globals; no allocation allowed)
__device__ __half g_A[(size_t)N_NODES * KTOT];   // [N,1152] fp16 A
__device__ __half g_BT[128 * KTOT];              // [n=128, k=1152] fp16 W^T
__device__ int g_cnt[NR];
__device__ int g_cur[NR];
__device__ int g_off[NR];
__device__ int g_bsum[NSCAN + 1];
__device__ int g_eidx[E_EDGES];
__device__ int g_tile_ctr;                       // persistent-GEMM work counter

__device__ __forceinline__ uint32_t smem_u32(const void* p) {
    uint32_t a;
    asm("{ .reg .u64 t; cvta.to.shared.u64 t, %1; cvt.u32.u64 %0, t; }" : "=r"(a) : "l"(p));
    return a;
}
__device__ __forceinline__ void cp16(uint32_t dst, const void* src, int sz) {
    asm volatile("cp.async.cg.shared.global [%0], [%1], 16, %2;"
                 :: "r"(dst), "l"(src), "r"(sz) : "memory");
}

// ---------------------------------------------------------------------------
// CSR build: zero counters, histogram, scan, fill
// ---------------------------------------------------------------------------
__global__ void zero_cnt_kernel() {
    const int i = blockIdx.x * blockDim.x + threadIdx.x;
    if (i < NR) { g_cnt[i] = 0; g_cur[i] = 0; }
    if (i == 0) g_tile_ctr = 0;
}

__global__ void hist_kernel(const int* __restrict__ nout, const int* __restrict__ rel) {
    const int e = blockIdx.x * blockDim.x + threadIdx.x;
    if (e < E_EDGES) atomicAdd(&g_cnt[nout[e] * R_REL + rel[e]], 1);
}

__global__ void scan1_kernel() {
    __shared__ int sd[256];
    const int t = threadIdx.x;
    const int base = blockIdx.x * SCAN_BLK + t * 16;
    int v[16], sum = 0;
    #pragma unroll
    for (int j = 0; j < 16; j++) {
        v[j] = sum;
        const int idx = base + j;
        sum += (idx < NR) ? g_cnt[idx] : 0;
    }
    sd[t] = sum;
    __syncthreads();
    #pragma unroll
    for (int d = 1; d < 256; d <<= 1) {
        int val = sd[t];
        if (t >= d) val += sd[t - d];
        __syncthreads();
        sd[t] = val;
        __syncthreads();
    }
    const int excl = sd[t] - sum;
    #pragma unroll
    for (int j = 0; j < 16; j++) {
        const int idx = base + j;
        if (idx < NR) g_off[idx] = excl + v[j];
    }
    if (t == 255) g_bsum[blockIdx.x] = sd[255];
}

__global__ void scan2_kernel() {
    __shared__ int sd[128];
    const int t = threadIdx.x;
    const int orig = (t < NSCAN) ? g_bsum[t] : 0;
    sd[t] = orig;
    __syncthreads();
    #pragma unroll
    for (int d = 1; d < 128; d <<= 1) {
        int val = sd[t];
        if (t >= d) val += sd[t - d];
        __syncthreads();
        sd[t] = val;
        __syncthreads();
    }
    if (t < NSCAN) g_bsum[t] = sd[t] - orig;
}

__global__ void scan3_kernel() {
    const int i = blockIdx.x * blockDim.x + threadIdx.x;
    if (i < NR) g_off[i] += g_bsum[i / SCAN_BLK];
}

__global__ void fill_kernel(const int* __restrict__ nout, const int* __restrict__ rel) {
    const int e = blockIdx.x * blockDim.x + threadIdx.x;
    if (e >= E_EDGES) return;
    const int seg = nout[e] * R_REL + rel[e];
    const int pos = g_off[seg] + atomicAdd(&g_cur[seg], 1);
    g_eidx[pos] = e;
}

// ---------------------------------------------------------------------------
// Prep: fp16 transposed weights into g_BT[n][k]
// ---------------------------------------------------------------------------
__global__ void prep_w_kernel(const float* __restrict__ Wlin, const float* __restrict__ Wloop) {
    const int idx = blockIdx.x * blockDim.x + threadIdx.x;
    if (idx >= 128 * KTOT) return;
    const int n = idx / KTOT;
    const int k = idx % KTOT;
    const float v = (k < KA) ? Wlin[(size_t)k * 128 + n] : Wloop[(size_t)(k - KA) * 128 + n];
    g_BT[idx] = __float2half_rn(v);
}

// ---------------------------------------------------------------------------
// Aggregate: warp per segment; writes fp16 mean; r==0 warp also copies x row
// ---------------------------------------------------------------------------
__global__ void aggregate_kernel(const float* __restrict__ x,
                                 const float* __restrict__ ew,
                                 const int* __restrict__ nin) {
    const int seg = (blockIdx.x * blockDim.x + threadIdx.x) >> 5;
    const int lane = threadIdx.x & 31;
    if (seg >= NR) return;

    const int node = seg >> 3;
    const int r = seg & 7;

    if (r == 0) {   // copy x row into g_A cols 1024..1151 (fp16)
        const float4 xv = *reinterpret_cast<const float4*>(x + (size_t)node * D + lane * 4);
        __half2 h0 = __floats2half2_rn(xv.x, xv.y);
        __half2 h1 = __floats2half2_rn(xv.z, xv.w);
        uint2 o;
        o.x = *reinterpret_cast<uint32_t*>(&h0);
        o.y = *reinterpret_cast<uint32_t*>(&h1);
        *reinterpret_cast<uint2*>(g_A + (size_t)node * KTOT + KA + lane * 4) = o;
    }

    const int start = g_off[seg];
    const int cnt = g_cnt[seg];

    float4 acc = make_float4(0.f, 0.f, 0.f, 0.f);
    float den = 0.f;
    int i = 0;
    for (; i + 2 <= cnt; i += 2) {
        const int e0 = g_eidx[start + i];
        const int e1 = g_eidx[start + i + 1];
        const float w0 = ew[e0], w1 = ew[e1];
        const int v0 = nin[e0], v1 = nin[e1];
        const float4 x0 = *reinterpret_cast<const float4*>(x + (size_t)v0 * D + lane * 4);
        const float4 x1 = *reinterpret_cast<const float4*>(x + (size_t)v1 * D + lane * 4);
        acc.x += w0 * x0.x + w1 * x1.x;
        acc.y += w0 * x0.y + w1 * x1.y;
        acc.z += w0 * x0.z + w1 * x1.z;
        acc.w += w0 * x0.w + w1 * x1.w;
        den += w0 + w1;
    }
    if (i < cnt) {
        const int e0 = g_eidx[start + i];
        const float w0 = ew[e0];
        const int v0 = nin[e0];
        const float4 x0 = *reinterpret_cast<const float4*>(x + (size_t)v0 * D + lane * 4);
        acc.x += w0 * x0.x; acc.y += w0 * x0.y;
        acc.z += w0 * x0.z; acc.w += w0 * x0.w;
        den += w0;
    }
    const float s = 1.0f / (den + 1e-10f);
    __half2 h0 = __floats2half2_rn(acc.x * s, acc.y * s);
    __half2 h1 = __floats2half2_rn(acc.z * s, acc.w * s);
    uint2 o;
    o.x = *reinterpret_cast<uint32_t*>(&h0);
    o.y = *reinterpret_cast<uint32_t*>(&h1);
    *reinterpret_cast<uint2*>(g_A + (size_t)node * KTOT + r * 128 + lane * 4) = o;
}

// ---------------------------------------------------------------------------
// FP16 GEMM, persistent single wave:
// out = relu( g_A @ g_BT^T + bias ).  m16n8k16, fp32 accumulate.
// BM=BN=128, BK=32/stage, NSTG=5, 4 stages in flight, 296 blocks, tile counter.
// Tile rows stored [row][k], 80 B stride (64 B data + 16 pad; conflict-free).
// ---------------------------------------------------------------------------
#define TS_B 80                         // bytes per tile row (32 fp16 + 8 pad)
#define STG_B (128 * TS_B)              // 10240 B per stage per operand
#define NSTG 5
#define AS_OFF 0
#define BS_OFF (NSTG * STG_B)           // 51200
#define BIAS_OFF (2 * NSTG * STG_B)     // 102400
#define SM_TOTAL (BIAS_OFF + 768)
#define NIT (KTOT / 32)                 // 36 stages per tile

#define LDSM4(R0, R1, R2, R3, ADDR)                                             \
    asm volatile("ldmatrix.sync.aligned.m8n8.x4.shared.b16 {%0,%1,%2,%3}, [%4];"\
                 : "=r"(R0), "=r"(R1), "=r"(R2), "=r"(R3) : "r"(ADDR))
#define LDSM2(R0, R1, ADDR)                                                     \
    asm volatile("ldmatrix.sync.aligned.m8n8.x2.shared.b16 {%0,%1}, [%2];"      \
                 : "=r"(R0), "=r"(R1) : "r"(ADDR))
#define MMA16(CC, A0, A1, A2, A3, B0, B1)                                       \
    asm volatile(                                                               \
        "mma.sync.aligned.m16n8k16.row.col.f32.f16.f16.f32 "                    \
        "{%0,%1,%2,%3}, {%4,%5,%6,%7}, {%8,%9}, {%0,%1,%2,%3};\n"               \
        : "+f"(CC[0]), "+f"(CC[1]), "+f"(CC[2]), "+f"(CC[3])                    \
        : "r"(A0), "r"(A1), "r"(A2), "r"(A3), "r"(B0), "r"(B1))

__global__ __launch_bounds__(256, 2)
void gemm_fp16(const float* __restrict__ blin, const float* __restrict__ bloop,
               float* __restrict__ out) {
    extern __shared__ char smem[];
    float* bias_s = reinterpret_cast<float*>(smem + BIAS_OFF);
    int* s_tile = reinterpret_cast<int*>(smem + BIAS_OFF + 512);
    const uint32_t smb = smem_u32(smem);

    const int tid  = threadIdx.x;
    if (tid < 128) bias_s[tid] = blin[tid] + bloop[tid];

    const int lane = tid & 31;
    const int wid  = tid >> 5;
    const int g = lane >> 2;
    const int t = lane & 3;
    const int wm = wid >> 2;     // 0..1, 64 rows
    const int wn = wid & 3;      // 0..3, 32 cols

    // cp.async: stage = 128 rows x 64 B = 512 chunks; thread -> chunks 2tid,2tid+1
    const int r0c = tid >> 1;                  // row (0..127)
    const int q0  = (tid & 1) * 2;             // quarter 0 or 2
    const int q1  = q0 + 1;                    // quarter 1 or 3
    const size_t brow_off = (size_t)r0c * KTOT;   // halfs

    // ldmatrix base offsets (bytes within a stage tile)
    const int lm_row = (lane & 7) + ((lane >> 3) & 1) * 8;
    const int a_base = (wm * 64 + lm_row) * TS_B + ((lane >> 4) & 1) * 16;
    const int lb = lane & 15;
    const int b_base = (wn * 32 + (lb & 7)) * TS_B + ((lb >> 3) & 1) * 16;

    for (;;) {
        __syncthreads();                       // protect s_tile + smem reuse
        if (tid == 0) *s_tile = atomicAdd(&g_tile_ctr, 1);
        __syncthreads();
        const int tile = *s_tile;
        if (tile >= NTILES) break;

        const int n0blk = tile * 128;
        const int grow = n0blk + r0c;
        const int asz = (grow < N_NODES) ? 16 : 0;
        const size_t arow_off = (size_t)min(grow, N_NODES - 1) * KTOT;   // halfs

#define ISSUE(ST, K0) do {                                                       \
    const uint32_t ab = smb + AS_OFF + (ST) * STG_B + r0c * TS_B;                \
    const uint32_t bb = smb + BS_OFF + (ST) * STG_B + r0c * TS_B;                \
    cp16(ab + q0 * 16, g_A + arow_off + (K0) + q0 * 8, asz);                     \
    cp16(ab + q1 * 16, g_A + arow_off + (K0) + q1 * 8, asz);                     \
    cp16(bb + q0 * 16, g_BT + brow_off + (K0) + q0 * 8, 16);                     \
    cp16(bb + q1 * 16, g_BT + brow_off + (K0) + q1 * 8, 16);                     \
    asm volatile("cp.async.commit_group;" ::: "memory");                         \
} while (0)

        float c[4][4][4];
        #pragma unroll
        for (int mt = 0; mt < 4; mt++)
            #pragma unroll
            for (int nt = 0; nt < 4; nt++)
                #pragma unroll
                for (int q = 0; q < 4; q++) c[mt][nt][q] = 0.f;

        ISSUE(0, 0);
        ISSUE(1, 32);
        ISSUE(2, 64);
        ISSUE(3, 96);

        for (int it = 0; it < NIT; it++) {
            const int st = it % NSTG;
            const int rem = NIT - 1 - it;
            if (rem >= 3)      asm volatile("cp.async.wait_group 3;" ::: "memory");
            else if (rem == 2) asm volatile("cp.async.wait_group 2;" ::: "memory");
            else if (rem == 1) asm volatile("cp.async.wait_group 1;" ::: "memory");
            else               asm volatile("cp.async.wait_group 0;" ::: "memory");
            __syncthreads();
            if (it + 4 < NIT) ISSUE((it + 4) % NSTG, (it + 4) * 32);

            const uint32_t ab = smb + AS_OFF + st * STG_B + a_base;
            const uint32_t bb = smb + BS_OFF + st * STG_B + b_base;
            #pragma unroll
            for (int ks = 0; ks < 2; ks++) {            // two k16 steps per stage
                uint32_t a[4][4], b[4][2];
                #pragma unroll
                for (int mt = 0; mt < 4; mt++)
                    LDSM4(a[mt][0], a[mt][1], a[mt][2], a[mt][3],
                          ab + mt * 16 * TS_B + ks * 32);
                #pragma unroll
                for (int nt = 0; nt < 4; nt++)
                    LDSM2(b[nt][0], b[nt][1], bb + nt * 8 * TS_B + ks * 32);
                #pragma unroll
                for (int mt = 0; mt < 4; mt++)
                    #pragma unroll
                    for (int nt = 0; nt < 4; nt++)
                        MMA16(c[mt][nt], a[mt][0], a[mt][1], a[mt][2], a[mt][3],
                              b[nt][0], b[nt][1]);
            }
        }

        // Epilogue: bias + relu + store
        #pragma unroll
        for (int mt = 0; mt < 4; mt++) {
            const int r0 = n0blk + wm * 64 + mt * 16 + g;
            const int r1 = r0 + 8;
            #pragma unroll
            for (int nt = 0; nt < 4; nt++) {
                const int cn = wn * 32 + nt * 8 + 2 * t;
                const float b0 = bias_s[cn], b1 = bias_s[cn + 1];
                if (r0 < N_NODES) {
                    float2 v;
                    v.x = fmaxf(c[mt][nt][0] + b0, 0.f);
                    v.y = fmaxf(c[mt][nt][1] + b1, 0.f);
                    *reinterpret_cast<float2*>(out + (size_t)r0 * 128 + cn) = v;
                }
                if (r1 < N_NODES) {
                    float2 v;
                    v.x = fmaxf(c[mt][nt][2] + b0, 0.f);
                    v.y = fmaxf(c[mt][nt][3] + b1, 0.f);
                    *reinterpret_cast<float2*>(out + (size_t)r1 * 128 + cn) = v;
                }
            }
        }
    }
}

// ---------------------------------------------------------------------------
// Launch. Inputs: 0:x 1:edge_weight 2:W_lin 3:b_lin 4:W_loop 5:b_loop
//                 6:node_in 7:node_out 8:relation
// ---------------------------------------------------------------------------
extern "C" void kernel_launch(void* const* d_in, const int* in_sizes, int n_in,
                              void* d_out, int out_size) {
    const float* x     = (const float*)d_in[0];
    const float* ew    = (const float*)d_in[1];
    const float* Wlin  = (const float*)d_in[2];
    const float* blin  = (const float*)d_in[3];
    const float* Wloop = (const float*)d_in[4];
    const float* bloop = (const float*)d_in[5];
    const int* nin     = (const int*)d_in[6];
    const int* nout    = (const int*)d_in[7];
    const int* rel     = (const int*)d_in[8];
    float* out         = (float*)d_out;

    cudaFuncSetAttribute(gemm_fp16, cudaFuncAttributeMaxDynamicSharedMemorySize, SM_TOTAL);

    zero_cnt_kernel<<<(NR + 255) / 256, 256>>>();
    hist_kernel<<<(E_EDGES + 255) / 256, 256>>>(nout, rel);
    prep_w_kernel<<<(128 * KTOT + 255) / 256, 256>>>(Wlin, Wloop);
    scan1_kernel<<<NSCAN, 256>>>();
    scan2_kernel<<<1, 128>>>();
    scan3_kernel<<<(NR + 255) / 256, 256>>>();
    fill_kernel<<<(E_EDGES + 255) / 256, 256>>>(nout, rel);
    aggregate_kernel<<<NR / 8, 256>>>(x, ew, nin);
    gemm_fp16<<<296, 256, SM_TOTAL>>>(blin, bloop, out);
}

// round 13
// speedup vs baseline: 1.3874x; 1.0090x over previous
#include <cuda_runtime.h>
#include <cuda_fp16.h>
#include <cstdint>

#define N_NODES 50000
#define D 128
#define R_REL 8
#define E_EDGES 800000
#define NR (N_NODES * R_REL)   // 400000
#define KTOT 1152              // R*D + D
#define KA 1024                // R*D
#define NTILES 391             // M tiles of 128

#define SCAN_BLK 4096
#define NSCAN ((NR + SCAN_BLK - 1) / SCAN_BLK)   // 98

// Scratch (__device__ globals; no allocation allowed)
__device__ __half g_A[(size_t)N_NODES * KTOT];   // [N,1152] fp16 A
__device__ __half g_BT[128 * KTOT];              // [n=128, k=1152] fp16 W^T
__device__ int g_cnt[NR];
__device__ int g_cur[NR];
__device__ int g_off[NR];
__device__ int g_bsum[NSCAN + 1];
__device__ int g_eidx[E_EDGES];
__device__ int g_tile_ctr;                       // persistent-GEMM work counter

__device__ __forceinline__ uint32_t smem_u32(const void* p) {
    uint32_t a;
    asm("{ .reg .u64 t; cvta.to.shared.u64 t, %1; cvt.u32.u64 %0, t; }" : "=r"(a) : "l"(p));
    return a;
}
__device__ __forceinline__ void cp16(uint32_t dst, const void* src, int sz) {
    asm volatile("cp.async.cg.shared.global [%0], [%1], 16, %2;"
                 :: "r"(dst), "l"(src), "r"(sz) : "memory");
}

// ---------------------------------------------------------------------------
// CSR build: zero counters, histogram, scan, fill
// ---------------------------------------------------------------------------
__global__ void zero_cnt_kernel() {
    const int i = blockIdx.x * blockDim.x + threadIdx.x;
    if (i < NR) { g_cnt[i] = 0; g_cur[i] = 0; }
    if (i == 0) g_tile_ctr = 0;
}

__global__ void hist_kernel(const int* __restrict__ nout, const int* __restrict__ rel) {
    const int e = blockIdx.x * blockDim.x + threadIdx.x;
    if (e < E_EDGES) atomicAdd(&g_cnt[nout[e] * R_REL + rel[e]], 1);
}

__global__ void scan1_kernel() {
    __shared__ int sd[256];
    const int t = threadIdx.x;
    const int base = blockIdx.x * SCAN_BLK + t * 16;
    int v[16], sum = 0;
    #pragma unroll
    for (int j = 0; j < 16; j++) {
        v[j] = sum;
        const int idx = base + j;
        sum += (idx < NR) ? g_cnt[idx] : 0;
    }
    sd[t] = sum;
    __syncthreads();
    #pragma unroll
    for (int d = 1; d < 256; d <<= 1) {
        int val = sd[t];
        if (t >= d) val += sd[t - d];
        __syncthreads();
        sd[t] = val;
        __syncthreads();
    }
    const int excl = sd[t] - sum;
    #pragma unroll
    for (int j = 0; j < 16; j++) {
        const int idx = base + j;
        if (idx < NR) g_off[idx] = excl + v[j];
    }
    if (t == 255) g_bsum[blockIdx.x] = sd[255];
}

__global__ void scan2_kernel() {
    __shared__ int sd[128];
    const int t = threadIdx.x;
    const int orig = (t < NSCAN) ? g_bsum[t] : 0;
    sd[t] = orig;
    __syncthreads();
    #pragma unroll
    for (int d = 1; d < 128; d <<= 1) {
        int val = sd[t];
        if (t >= d) val += sd[t - d];
        __syncthreads();
        sd[t] = val;
        __syncthreads();
    }
    if (t < NSCAN) g_bsum[t] = sd[t] - orig;
}

__global__ void scan3_kernel() {
    const int i = blockIdx.x * blockDim.x + threadIdx.x;
    if (i < NR) g_off[i] += g_bsum[i / SCAN_BLK];
}

__global__ void fill_kernel(const int* __restrict__ nout, const int* __restrict__ rel) {
    const int e = blockIdx.x * blockDim.x + threadIdx.x;
    if (e >= E_EDGES) return;
    const int seg = nout[e] * R_REL + rel[e];
    const int pos = g_off[seg] + atomicAdd(&g_cur[seg], 1);
    g_eidx[pos] = e;
}

// ---------------------------------------------------------------------------
// Prep: fp16 transposed weights into g_BT[n][k]
// ---------------------------------------------------------------------------
__global__ void prep_w_kernel(const float* __restrict__ Wlin, const float* __restrict__ Wloop) {
    const int idx = blockIdx.x * blockDim.x + threadIdx.x;
    if (idx >= 128 * KTOT) return;
    const int n = idx / KTOT;
    const int k = idx % KTOT;
    const float v = (k < KA) ? Wlin[(size_t)k * 128 + n] : Wloop[(size_t)(k - KA) * 128 + n];
    g_BT[idx] = __float2half_rn(v);
}

// ---------------------------------------------------------------------------
// Aggregate: warp per segment; writes fp16 mean; r==0 warp also copies x row
// ---------------------------------------------------------------------------
__global__ void aggregate_kernel(const float* __restrict__ x,
                                 const float* __restrict__ ew,
                                 const int* __restrict__ nin) {
    const int seg = (blockIdx.x * blockDim.x + threadIdx.x) >> 5;
    const int lane = threadIdx.x & 31;
    if (seg >= NR) return;

    const int node = seg >> 3;
    const int r = seg & 7;

    if (r == 0) {   // copy x row into g_A cols 1024..1151 (fp16)
        const float4 xv = *reinterpret_cast<const float4*>(x + (size_t)node * D + lane * 4);
        __half2 h0 = __floats2half2_rn(xv.x, xv.y);
        __half2 h1 = __floats2half2_rn(xv.z, xv.w);
        uint2 o;
        o.x = *reinterpret_cast<uint32_t*>(&h0);
        o.y = *reinterpret_cast<uint32_t*>(&h1);
        *reinterpret_cast<uint2*>(g_A + (size_t)node * KTOT + KA + lane * 4) = o;
    }

    const int start = g_off[seg];
    const int cnt = g_cnt[seg];

    float4 acc = make_float4(0.f, 0.f, 0.f, 0.f);
    float den = 0.f;
    int i = 0;
    for (; i + 2 <= cnt; i += 2) {
        const int e0 = g_eidx[start + i];
        const int e1 = g_eidx[start + i + 1];
        const float w0 = ew[e0], w1 = ew[e1];
        const int v0 = nin[e0], v1 = nin[e1];
        const float4 x0 = *reinterpret_cast<const float4*>(x + (size_t)v0 * D + lane * 4);
        const float4 x1 = *reinterpret_cast<const float4*>(x + (size_t)v1 * D + lane * 4);
        acc.x += w0 * x0.x + w1 * x1.x;
        acc.y += w0 * x0.y + w1 * x1.y;
        acc.z += w0 * x0.z + w1 * x1.z;
        acc.w += w0 * x0.w + w1 * x1.w;
        den += w0 + w1;
    }
    if (i < cnt) {
        const int e0 = g_eidx[start + i];
        const float w0 = ew[e0];
        const int v0 = nin[e0];
        const float4 x0 = *reinterpret_cast<const float4*>(x + (size_t)v0 * D + lane * 4);
        acc.x += w0 * x0.x; acc.y += w0 * x0.y;
        acc.z += w0 * x0.z; acc.w += w0 * x0.w;
        den += w0;
    }
    const float s = 1.0f / (den + 1e-10f);
    __half2 h0 = __floats2half2_rn(acc.x * s, acc.y * s);
    __half2 h1 = __floats2half2_rn(acc.z * s, acc.w * s);
    uint2 o;
    o.x = *reinterpret_cast<uint32_t*>(&h0);
    o.y = *reinterpret_cast<uint32_t*>(&h1);
    *reinterpret_cast<uint2*>(g_A + (size_t)node * KTOT + r * 128 + lane * 4) = o;
}

// ---------------------------------------------------------------------------
// FP16 GEMM, persistent single wave:
// out = relu( g_A @ g_BT^T + bias ).  m16n8k16, fp32 accumulate.
// BM=BN=128, BK=32/stage, NSTG=5, 4 stages in flight, 296 blocks, tile counter.
// Tile rows stored [row][k], 80 B stride (64 B data + 16 pad; conflict-free).
// ---------------------------------------------------------------------------
#define TS_B 80                         // bytes per tile row (32 fp16 + 8 pad)
#define STG_B (128 * TS_B)              // 10240 B per stage per operand
#define NSTG 5
#define AS_OFF 0
#define BS_OFF (NSTG * STG_B)           // 51200
#define BIAS_OFF (2 * NSTG * STG_B)     // 102400
#define SM_TOTAL (BIAS_OFF + 768)
#define NIT (KTOT / 32)                 // 36 stages per tile

#define LDSM4(R0, R1, R2, R3, ADDR)                                             \
    asm volatile("ldmatrix.sync.aligned.m8n8.x4.shared.b16 {%0,%1,%2,%3}, [%4];"\
                 : "=r"(R0), "=r"(R1), "=r"(R2), "=r"(R3) : "r"(ADDR))
#define LDSM2(R0, R1, ADDR)                                                     \
    asm volatile("ldmatrix.sync.aligned.m8n8.x2.shared.b16 {%0,%1}, [%2];"      \
                 : "=r"(R0), "=r"(R1) : "r"(ADDR))
#define MMA16(CC, A0, A1, A2, A3, B0, B1)                                       \
    asm volatile(                                                               \
        "mma.sync.aligned.m16n8k16.row.col.f32.f16.f16.f32 "                    \
        "{%0,%1,%2,%3}, {%4,%5,%6,%7}, {%8,%9}, {%0,%1,%2,%3};\n"               \
        : "+f"(CC[0]), "+f"(CC[1]), "+f"(CC[2]), "+f"(CC[3])                    \
        : "r"(A0), "r"(A1), "r"(A2), "r"(A3), "r"(B0), "r"(B1))

__global__ __launch_bounds__(256, 2)
void gemm_fp16(const float* __restrict__ blin, const float* __restrict__ bloop,
               float* __restrict__ out) {
    extern __shared__ char smem[];
    float* bias_s = reinterpret_cast<float*>(smem + BIAS_OFF);
    int* s_tile = reinterpret_cast<int*>(smem + BIAS_OFF + 512);
    const uint32_t smb = smem_u32(smem);

    const int tid  = threadIdx.x;
    if (tid < 128) bias_s[tid] = blin[tid] + bloop[tid];

    const int lane = tid & 31;
    const int wid  = tid >> 5;
    const int g = lane >> 2;
    const int t = lane & 3;
    const int wm = wid >> 2;     // 0..1, 64 rows
    const int wn = wid & 3;      // 0..3, 32 cols

    // cp.async: stage = 128 rows x 64 B = 512 chunks; thread -> chunks 2tid,2tid+1
    const int r0c = tid >> 1;                  // row (0..127)
    const int q0  = (tid & 1) * 2;             // quarter 0 or 2
    const int q1  = q0 + 1;                    // quarter 1 or 3
    const size_t brow_off = (size_t)r0c * KTOT;   // halfs

    // ldmatrix base offsets (bytes within a stage tile)
    const int lm_row = (lane & 7) + ((lane >> 3) & 1) * 8;
    const int a_base = (wm * 64 + lm_row) * TS_B + ((lane >> 4) & 1) * 16;
    const int lb = lane & 15;
    const int b_base = (wn * 32 + (lb & 7)) * TS_B + ((lb >> 3) & 1) * 16;

    for (;;) {
        __syncthreads();                       // protect s_tile + smem reuse
        if (tid == 0) *s_tile = atomicAdd(&g_tile_ctr, 1);
        __syncthreads();
        const int tile = *s_tile;
        if (tile >= NTILES) break;

        const int n0blk = tile * 128;
        const int grow = n0blk + r0c;
        const int asz = (grow < N_NODES) ? 16 : 0;
        const size_t arow_off = (size_t)min(grow, N_NODES - 1) * KTOT;   // halfs

#define ISSUE(ST, K0) do {                                                       \
    const uint32_t ab = smb + AS_OFF + (ST) * STG_B + r0c * TS_B;                \
    const uint32_t bb = smb + BS_OFF + (ST) * STG_B + r0c * TS_B;                \
    cp16(ab + q0 * 16, g_A + arow_off + (K0) + q0 * 8, asz);                     \
    cp16(ab + q1 * 16, g_A + arow_off + (K0) + q1 * 8, asz);                     \
    cp16(bb + q0 * 16, g_BT + brow_off + (K0) + q0 * 8, 16);                     \
    cp16(bb + q1 * 16, g_BT + brow_off + (K0) + q1 * 8, 16);                     \
    asm volatile("cp.async.commit_group;" ::: "memory");                         \
} while (0)

        float c[4][4][4];
        #pragma unroll
        for (int mt = 0; mt < 4; mt++)
            #pragma unroll
            for (int nt = 0; nt < 4; nt++)
                #pragma unroll
                for (int q = 0; q < 4; q++) c[mt][nt][q] = 0.f;

        ISSUE(0, 0);
        ISSUE(1, 32);
        ISSUE(2, 64);
        ISSUE(3, 96);

        for (int it = 0; it < NIT; it++) {
            const int st = it % NSTG;
            const int rem = NIT - 1 - it;
            if (rem >= 3)      asm volatile("cp.async.wait_group 3;" ::: "memory");
            else if (rem == 2) asm volatile("cp.async.wait_group 2;" ::: "memory");
            else if (rem == 1) asm volatile("cp.async.wait_group 1;" ::: "memory");
            else               asm volatile("cp.async.wait_group 0;" ::: "memory");
            __syncthreads();
            if (it + 4 < NIT) ISSUE((it + 4) % NSTG, (it + 4) * 32);

            const uint32_t ab = smb + AS_OFF + st * STG_B + a_base;
            const uint32_t bb = smb + BS_OFF + st * STG_B + b_base;
            #pragma unroll
            for (int ks = 0; ks < 2; ks++) {            // two k16 steps per stage
                uint32_t a[4][4], b[4][2];
                #pragma unroll
                for (int mt = 0; mt < 4; mt++)
                    LDSM4(a[mt][0], a[mt][1], a[mt][2], a[mt][3],
                          ab + mt * 16 * TS_B + ks * 32);
                #pragma unroll
                for (int nt = 0; nt < 4; nt++)
                    LDSM2(b[nt][0], b[nt][1], bb + nt * 8 * TS_B + ks * 32);
                #pragma unroll
                for (int mt = 0; mt < 4; mt++)
                    #pragma unroll
                    for (int nt = 0; nt < 4; nt++)
                        MMA16(c[mt][nt], a[mt][0], a[mt][1], a[mt][2], a[mt][3],
                              b[nt][0], b[nt][1]);
            }
        }

        // Epilogue: bias + relu + store
        #pragma unroll
        for (int mt = 0; mt < 4; mt++) {
            const int r0 = n0blk + wm * 64 + mt * 16 + g;
            const int r1 = r0 + 8;
            #pragma unroll
            for (int nt = 0; nt < 4; nt++) {
                const int cn = wn * 32 + nt * 8 + 2 * t;
                const float b0 = bias_s[cn], b1 = bias_s[cn + 1];
                if (r0 < N_NODES) {
                    float2 v;
                    v.x = fmaxf(c[mt][nt][0] + b0, 0.f);
                    v.y = fmaxf(c[mt][nt][1] + b1, 0.f);
                    *reinterpret_cast<float2*>(out + (size_t)r0 * 128 + cn) = v;
                }
                if (r1 < N_NODES) {
                    float2 v;
                    v.x = fmaxf(c[mt][nt][2] + b0, 0.f);
                    v.y = fmaxf(c[mt][nt][3] + b1, 0.f);
                    *reinterpret_cast<float2*>(out + (size_t)r1 * 128 + cn) = v;
                }
            }
        }
    }
}

// ---------------------------------------------------------------------------
// Launch. Inputs: 0:x 1:edge_weight 2:W_lin 3:b_lin 4:W_loop 5:b_loop
//                 6:node_in 7:node_out 8:relation
// ---------------------------------------------------------------------------
extern "C" void kernel_launch(void* const* d_in, const int* in_sizes, int n_in,
                              void* d_out, int out_size) {
    const float* x     = (const float*)d_in[0];
    const float* ew    = (const float*)d_in[1];
    const float* Wlin  = (const float*)d_in[2];
    const float* blin  = (const float*)d_in[3];
    const float* Wloop = (const float*)d_in[4];
    const float* bloop = (const float*)d_in[5];
    const int* nin     = (const int*)d_in[6];
    const int* nout    = (const int*)d_in[7];
    const int* rel     = (const int*)d_in[8];
    float* out         = (float*)d_out;

    cudaFuncSetAttribute(gemm_fp16, cudaFuncAttributeMaxDynamicSharedMemorySize, SM_TOTAL);

    zero_cnt_kernel<<<(NR + 255) / 256, 256>>>();
    hist_kernel<<<(E_EDGES + 255) / 256, 256>>>(nout, rel);
    prep_w_kernel<<<(128 * KTOT + 255) / 256, 256>>>(Wlin, Wloop);
    scan1_kernel<<<NSCAN, 256>>>();
    scan2_kernel<<<1, 128>>>();
    scan3_kernel<<<(NR + 255) / 256, 256>>>();
    fill_kernel<<<(E_EDGES + 255) / 256, 256>>>(nout, rel);
    aggregate_kernel<<<NR / 8, 256>>>(x, ew, nin);
    gemm_fp16<<<296, 256, SM_TOTAL>>>(blin, bloop, out);
}

// round 14
// speedup vs baseline: 1.4126x; 1.0182x over previous
#include <cuda_runtime.h>
#include <cuda_fp16.h>
#include <cstdint>

#define N_NODES 50000
#define D 128
#define R_REL 8
#define E_EDGES 800000
#define NR (N_NODES * R_REL)   // 400000
#define KTOT 1152              // R*D + D
#define KA 1024                // R*D
#define NTILES 391             // M tiles of 128

#define SCAN_BLK 4096
#define NSCAN ((NR + SCAN_BLK - 1) / SCAN_BLK)   // 98

// Scratch (__device__ globals; no allocation allowed)
__device__ __half g_A[(size_t)N_NODES * KTOT];   // [N,1152] fp16 A
__device__ __half g_BT[128 * KTOT];              // [n=128, k=1152] fp16 W^T
__device__ int g_cnt[NR];
__device__ int g_off[NR];                        // block-local excl scan; fill bumps it
__device__ int g_bsum[NSCAN + 1];                // block sums -> exclusive prefix (last-block scan)
__device__ int g_eidx[E_EDGES];
__device__ int g_tile_ctr;                       // persistent-GEMM work counter
__device__ int g_scan_ctr;                       // scan1 last-block counter

__device__ __forceinline__ uint32_t smem_u32(const void* p) {
    uint32_t a;
    asm("{ .reg .u64 t; cvta.to.shared.u64 t, %1; cvt.u32.u64 %0, t; }" : "=r"(a) : "l"(p));
    return a;
}
__device__ __forceinline__ void cp16(uint32_t dst, const void* src, int sz) {
    asm volatile("cp.async.cg.shared.global [%0], [%1], 16, %2;"
                 :: "r"(dst), "l"(src), "r"(sz) : "memory");
}

// ---------------------------------------------------------------------------
// Init: zero g_cnt + counters, AND build fp16 transposed weights
// ---------------------------------------------------------------------------
__global__ void init_kernel(const float* __restrict__ Wlin, const float* __restrict__ Wloop) {
    const int i = blockIdx.x * blockDim.x + threadIdx.x;
    if (i < NR) g_cnt[i] = 0;
    if (i == 0) { g_tile_ctr = 0; g_scan_ctr = 0; }
    if (i < 128 * KTOT) {
        const int n = i / KTOT;
        const int k = i % KTOT;
        const float v = (k < KA) ? Wlin[(size_t)k * 128 + n]
                                 : Wloop[(size_t)(k - KA) * 128 + n];
        g_BT[i] = __float2half_rn(v);
    }
}

// ---------------------------------------------------------------------------
// Histogram: 4 edges per thread, vector loads
// ---------------------------------------------------------------------------
__global__ void hist_kernel(const int* __restrict__ nout, const int* __restrict__ rel) {
    const int e4 = blockIdx.x * blockDim.x + threadIdx.x;
    if (e4 >= E_EDGES / 4) return;
    const int4 no = reinterpret_cast<const int4*>(nout)[e4];
    const int4 re = reinterpret_cast<const int4*>(rel)[e4];
    atomicAdd(&g_cnt[no.x * R_REL + re.x], 1);
    atomicAdd(&g_cnt[no.y * R_REL + re.y], 1);
    atomicAdd(&g_cnt[no.z * R_REL + re.z], 1);
    atomicAdd(&g_cnt[no.w * R_REL + re.w], 1);
}

// ---------------------------------------------------------------------------
// Scan: per-block exclusive scan into g_off, block sums into g_bsum;
// the LAST block to finish also exclusive-scans g_bsum in place.
// ---------------------------------------------------------------------------
__global__ void scan_kernel() {
    __shared__ int sd[256];
    __shared__ int is_last;
    const int t = threadIdx.x;
    const int base = blockIdx.x * SCAN_BLK + t * 16;
    int v[16], sum = 0;
    #pragma unroll
    for (int j = 0; j < 16; j++) {
        v[j] = sum;
        const int idx = base + j;
        sum += (idx < NR) ? g_cnt[idx] : 0;
    }
    sd[t] = sum;
    __syncthreads();
    #pragma unroll
    for (int d = 1; d < 256; d <<= 1) {
        int val = sd[t];
        if (t >= d) val += sd[t - d];
        __syncthreads();
        sd[t] = val;
        __syncthreads();
    }
    const int excl = sd[t] - sum;
    #pragma unroll
    for (int j = 0; j < 16; j++) {
        const int idx = base + j;
        if (idx < NR) g_off[idx] = excl + v[j];
    }
    if (t == 255) g_bsum[blockIdx.x] = sd[255];

    // last-block tail: scan g_bsum
    __syncthreads();
    if (t == 0) {
        __threadfence();
        is_last = (atomicAdd(&g_scan_ctr, 1) == gridDim.x - 1) ? 1 : 0;
    }
    __syncthreads();
    if (is_last) {
        __shared__ int sb[128];
        if (t < 128) {
            const int orig = (t < NSCAN) ? g_bsum[t] : 0;
            sb[t] = orig;
            __syncwarp();
            // block-level Hillis-Steele over 128 entries (use syncthreads-free
            // path is unsafe across warps; do it with barriers on the 256-thread block)
        }
        __syncthreads();
        #pragma unroll
        for (int d = 1; d < 128; d <<= 1) {
            int val = 0;
            if (t < 128) {
                val = sb[t];
                if (t >= d) val += sb[t - d];
            }
            __syncthreads();
            if (t < 128) sb[t] = val;
            __syncthreads();
        }
        if (t < NSCAN) {
            const int orig = g_bsum[t];
            g_bsum[t] = sb[t] - orig;   // exclusive prefix
        }
    }
}

// ---------------------------------------------------------------------------
// Fill: bump g_off[seg] (local), absolute pos = local + bsum prefix
// ---------------------------------------------------------------------------
__global__ void fill_kernel(const int* __restrict__ nout, const int* __restrict__ rel) {
    const int e = blockIdx.x * blockDim.x + threadIdx.x;
    if (e >= E_EDGES) return;
    const int seg = nout[e] * R_REL + rel[e];
    const int pos = atomicAdd(&g_off[seg], 1) + g_bsum[seg >> 12];
    g_eidx[pos] = e;
}

// ---------------------------------------------------------------------------
// Aggregate: warp per segment; start = g_off[seg]-cnt+bsum (g_off was bumped
// by fill to local_start+cnt). Writes fp16 mean; r==0 warp also copies x row.
// ---------------------------------------------------------------------------
__global__ void aggregate_kernel(const float* __restrict__ x,
                                 const float* __restrict__ ew,
                                 const int* __restrict__ nin) {
    const int seg = (blockIdx.x * blockDim.x + threadIdx.x) >> 5;
    const int lane = threadIdx.x & 31;
    if (seg >= NR) return;

    const int node = seg >> 3;
    const int r = seg & 7;

    if (r == 0) {   // copy x row into g_A cols 1024..1151 (fp16)
        const float4 xv = *reinterpret_cast<const float4*>(x + (size_t)node * D + lane * 4);
        __half2 h0 = __floats2half2_rn(xv.x, xv.y);
        __half2 h1 = __floats2half2_rn(xv.z, xv.w);
        uint2 o;
        o.x = *reinterpret_cast<uint32_t*>(&h0);
        o.y = *reinterpret_cast<uint32_t*>(&h1);
        *reinterpret_cast<uint2*>(g_A + (size_t)node * KTOT + KA + lane * 4) = o;
    }

    const int cnt = g_cnt[seg];
    const int start = g_off[seg] - cnt + g_bsum[seg >> 12];

    float4 acc = make_float4(0.f, 0.f, 0.f, 0.f);
    float den = 0.f;
    int i = 0;
    for (; i + 2 <= cnt; i += 2) {
        const int e0 = g_eidx[start + i];
        const int e1 = g_eidx[start + i + 1];
        const float w0 = ew[e0], w1 = ew[e1];
        const int v0 = nin[e0], v1 = nin[e1];
        const float4 x0 = *reinterpret_cast<const float4*>(x + (size_t)v0 * D + lane * 4);
        const float4 x1 = *reinterpret_cast<const float4*>(x + (size_t)v1 * D + lane * 4);
        acc.x += w0 * x0.x + w1 * x1.x;
        acc.y += w0 * x0.y + w1 * x1.y;
        acc.z += w0 * x0.z + w1 * x1.z;
        acc.w += w0 * x0.w + w1 * x1.w;
        den += w0 + w1;
    }
    if (i < cnt) {
        const int e0 = g_eidx[start + i];
        const float w0 = ew[e0];
        const int v0 = nin[e0];
        const float4 x0 = *reinterpret_cast<const float4*>(x + (size_t)v0 * D + lane * 4);
        acc.x += w0 * x0.x; acc.y += w0 * x0.y;
        acc.z += w0 * x0.z; acc.w += w0 * x0.w;
        den += w0;
    }
    const float s = 1.0f / (den + 1e-10f);
    __half2 h0 = __floats2half2_rn(acc.x * s, acc.y * s);
    __half2 h1 = __floats2half2_rn(acc.z * s, acc.w * s);
    uint2 o;
    o.x = *reinterpret_cast<uint32_t*>(&h0);
    o.y = *reinterpret_cast<uint32_t*>(&h1);
    *reinterpret_cast<uint2*>(g_A + (size_t)node * KTOT + r * 128 + lane * 4) = o;
}

// ---------------------------------------------------------------------------
// FP16 GEMM, persistent single wave (unchanged from round 13):
// out = relu( g_A @ g_BT^T + bias ).  m16n8k16, fp32 accumulate.
// BM=BN=128, BK=32/stage, NSTG=5, 4 stages in flight, 296 blocks, tile counter.
// ---------------------------------------------------------------------------
#define TS_B 80
#define STG_B (128 * TS_B)
#define NSTG 5
#define AS_OFF 0
#define BS_OFF (NSTG * STG_B)
#define BIAS_OFF (2 * NSTG * STG_B)
#define SM_TOTAL (BIAS_OFF + 768)
#define NIT (KTOT / 32)

#define LDSM4(R0, R1, R2, R3, ADDR)                                             \
    asm volatile("ldmatrix.sync.aligned.m8n8.x4.shared.b16 {%0,%1,%2,%3}, [%4];"\
                 : "=r"(R0), "=r"(R1), "=r"(R2), "=r"(R3) : "r"(ADDR))
#define LDSM2(R0, R1, ADDR)                                                     \
    asm volatile("ldmatrix.sync.aligned.m8n8.x2.shared.b16 {%0,%1}, [%2];"      \
                 : "=r"(R0), "=r"(R1) : "r"(ADDR))
#define MMA16(CC, A0, A1, A2, A3, B0, B1)                                       \
    asm volatile(                                                               \
        "mma.sync.aligned.m16n8k16.row.col.f32.f16.f16.f32 "                    \
        "{%0,%1,%2,%3}, {%4,%5,%6,%7}, {%8,%9}, {%0,%1,%2,%3};\n"               \
        : "+f"(CC[0]), "+f"(CC[1]), "+f"(CC[2]), "+f"(CC[3])                    \
        : "r"(A0), "r"(A1), "r"(A2), "r"(A3), "r"(B0), "r"(B1))

__global__ __launch_bounds__(256, 2)
void gemm_fp16(const float* __restrict__ blin, const float* __restrict__ bloop,
               float* __restrict__ out) {
    extern __shared__ char smem[];
    float* bias_s = reinterpret_cast<float*>(smem + BIAS_OFF);
    int* s_tile = reinterpret_cast<int*>(smem + BIAS_OFF + 512);
    const uint32_t smb = smem_u32(smem);

    const int tid  = threadIdx.x;
    if (tid < 128) bias_s[tid] = blin[tid] + bloop[tid];

    const int lane = tid & 31;
    const int wid  = tid >> 5;
    const int g = lane >> 2;
    const int t = lane & 3;
    const int wm = wid >> 2;
    const int wn = wid & 3;

    const int r0c = tid >> 1;
    const int q0  = (tid & 1) * 2;
    const int q1  = q0 + 1;
    const size_t brow_off = (size_t)r0c * KTOT;

    const int lm_row = (lane & 7) + ((lane >> 3) & 1) * 8;
    const int a_base = (wm * 64 + lm_row) * TS_B + ((lane >> 4) & 1) * 16;
    const int lb = lane & 15;
    const int b_base = (wn * 32 + (lb & 7)) * TS_B + ((lb >> 3) & 1) * 16;

    for (;;) {
        __syncthreads();
        if (tid == 0) *s_tile = atomicAdd(&g_tile_ctr, 1);
        __syncthreads();
        const int tile = *s_tile;
        if (tile >= NTILES) break;

        const int n0blk = tile * 128;
        const int grow = n0blk + r0c;
        const int asz = (grow < N_NODES) ? 16 : 0;
        const size_t arow_off = (size_t)min(grow, N_NODES - 1) * KTOT;

#define ISSUE(ST, K0) do {                                                       \
    const uint32_t ab = smb + AS_OFF + (ST) * STG_B + r0c * TS_B;                \
    const uint32_t bb = smb + BS_OFF + (ST) * STG_B + r0c * TS_B;                \
    cp16(ab + q0 * 16, g_A + arow_off + (K0) + q0 * 8, asz);                     \
    cp16(ab + q1 * 16, g_A + arow_off + (K0) + q1 * 8, asz);                     \
    cp16(bb + q0 * 16, g_BT + brow_off + (K0) + q0 * 8, 16);                     \
    cp16(bb + q1 * 16, g_BT + brow_off + (K0) + q1 * 8, 16);                     \
    asm volatile("cp.async.commit_group;" ::: "memory");                         \
} while (0)

        float c[4][4][4];
        #pragma unroll
        for (int mt = 0; mt < 4; mt++)
            #pragma unroll
            for (int nt = 0; nt < 4; nt++)
                #pragma unroll
                for (int q = 0; q < 4; q++) c[mt][nt][q] = 0.f;

        ISSUE(0, 0);
        ISSUE(1, 32);
        ISSUE(2, 64);
        ISSUE(3, 96);

        for (int it = 0; it < NIT; it++) {
            const int st = it % NSTG;
            const int rem = NIT - 1 - it;
            if (rem >= 3)      asm volatile("cp.async.wait_group 3;" ::: "memory");
            else if (rem == 2) asm volatile("cp.async.wait_group 2;" ::: "memory");
            else if (rem == 1) asm volatile("cp.async.wait_group 1;" ::: "memory");
            else               asm volatile("cp.async.wait_group 0;" ::: "memory");
            __syncthreads();
            if (it + 4 < NIT) ISSUE((it + 4) % NSTG, (it + 4) * 32);

            const uint32_t ab = smb + AS_OFF + st * STG_B + a_base;
            const uint32_t bb = smb + BS_OFF + st * STG_B + b_base;
            #pragma unroll
            for (int ks = 0; ks < 2; ks++) {
                uint32_t a[4][4], b[4][2];
                #pragma unroll
                for (int mt = 0; mt < 4; mt++)
                    LDSM4(a[mt][0], a[mt][1], a[mt][2], a[mt][3],
                          ab + mt * 16 * TS_B + ks * 32);
                #pragma unroll
                for (int nt = 0; nt < 4; nt++)
                    LDSM2(b[nt][0], b[nt][1], bb + nt * 8 * TS_B + ks * 32);
                #pragma unroll
                for (int mt = 0; mt < 4; mt++)
                    #pragma unroll
                    for (int nt = 0; nt < 4; nt++)
                        MMA16(c[mt][nt], a[mt][0], a[mt][1], a[mt][2], a[mt][3],
                              b[nt][0], b[nt][1]);
            }
        }

        #pragma unroll
        for (int mt = 0; mt < 4; mt++) {
            const int r0 = n0blk + wm * 64 + mt * 16 + g;
            const int r1 = r0 + 8;
            #pragma unroll
            for (int nt = 0; nt < 4; nt++) {
                const int cn = wn * 32 + nt * 8 + 2 * t;
                const float b0 = bias_s[cn], b1 = bias_s[cn + 1];
                if (r0 < N_NODES) {
                    float2 v;
                    v.x = fmaxf(c[mt][nt][0] + b0, 0.f);
                    v.y = fmaxf(c[mt][nt][1] + b1, 0.f);
                    *reinterpret_cast<float2*>(out + (size_t)r0 * 128 + cn) = v;
                }
                if (r1 < N_NODES) {
                    float2 v;
                    v.x = fmaxf(c[mt][nt][2] + b0, 0.f);
                    v.y = fmaxf(c[mt][nt][3] + b1, 0.f);
                    *reinterpret_cast<float2*>(out + (size_t)r1 * 128 + cn) = v;
                }
            }
        }
    }
}

// ---------------------------------------------------------------------------
// Launch. Inputs: 0:x 1:edge_weight 2:W_lin 3:b_lin 4:W_loop 5:b_loop
//                 6:node_in 7:node_out 8:relation
// ---------------------------------------------------------------------------
extern "C" void kernel_launch(void* const* d_in, const int* in_sizes, int n_in,
                              void* d_out, int out_size) {
    const float* x     = (const float*)d_in[0];
    const float* ew    = (const float*)d_in[1];
    const float* Wlin  = (const float*)d_in[2];
    const float* blin  = (const float*)d_in[3];
    const float* Wloop = (const float*)d_in[4];
    const float* bloop = (const float*)d_in[5];
    const int* nin     = (const int*)d_in[6];
    const int* nout    = (const int*)d_in[7];
    const int* rel     = (const int*)d_in[8];
    float* out         = (float*)d_out;

    cudaFuncSetAttribute(gemm_fp16, cudaFuncAttributeMaxDynamicSharedMemorySize, SM_TOTAL);

    init_kernel<<<(NR + 255) / 256, 256>>>(Wlin, Wloop);
    hist_kernel<<<(E_EDGES / 4 + 255) / 256, 256>>>(nout, rel);
    scan_kernel<<<NSCAN, 256>>>();
    fill_kernel<<<(E_EDGES + 255) / 256, 256>>>(nout, rel);
    aggregate_kernel<<<NR / 8, 256>>>(x, ew, nin);
    gemm_fp16<<<296, 256, SM_TOTAL>>>(blin, bloop, out);
}

// round 15
// speedup vs baseline: 1.4128x; 1.0001x over previous
#include <cuda_runtime.h>
#include <cuda_fp16.h>
#include <cstdint>

#define N_NODES 50000
#define D 128
#define R_REL 8
#define E_EDGES 800000
#define NR (N_NODES * R_REL)   // 400000
#define KTOT 1152              // R*D + D
#define KA 1024                // R*D
#define NTILES 391             // M tiles of 128

#define SCAN_BLK 4096
#define NSCAN ((NR + SCAN_BLK - 1) / SCAN_BLK)   // 98

// Scratch (__device__ globals; no allocation allowed)
__device__ __half g_A[(size_t)N_NODES * KTOT];   // [N,1152] fp16 A
__device__ __half g_BT[128 * KTOT];              // [n=128, k=1152] fp16 W^T
__device__ int g_cnt[NR];
__device__ int g_off[NR];                        // block-local excl scan; fill bumps it
__device__ int g_bsum[NSCAN + 1];                // block sums -> exclusive prefix (last-block scan)
__device__ int g_eidx[E_EDGES];
__device__ int g_tile_ctr;                       // persistent-GEMM work counter
__device__ int g_scan_ctr;                       // scan1 last-block counter

__device__ __forceinline__ uint32_t smem_u32(const void* p) {
    uint32_t a;
    asm("{ .reg .u64 t; cvta.to.shared.u64 t, %1; cvt.u32.u64 %0, t; }" : "=r"(a) : "l"(p));
    return a;
}
__device__ __forceinline__ void cp16(uint32_t dst, const void* src, int sz) {
    asm volatile("cp.async.cg.shared.global [%0], [%1], 16, %2;"
                 :: "r"(dst), "l"(src), "r"(sz) : "memory");
}

// ---------------------------------------------------------------------------
// Init: zero g_cnt + counters, AND build fp16 transposed weights
// ---------------------------------------------------------------------------
__global__ void init_kernel(const float* __restrict__ Wlin, const float* __restrict__ Wloop) {
    const int i = blockIdx.x * blockDim.x + threadIdx.x;
    if (i < NR) g_cnt[i] = 0;
    if (i == 0) { g_tile_ctr = 0; g_scan_ctr = 0; }
    if (i < 128 * KTOT) {
        const int n = i / KTOT;
        const int k = i % KTOT;
        const float v = (k < KA) ? Wlin[(size_t)k * 128 + n]
                                 : Wloop[(size_t)(k - KA) * 128 + n];
        g_BT[i] = __float2half_rn(v);
    }
}

// ---------------------------------------------------------------------------
// Histogram: 4 edges per thread, vector loads
// ---------------------------------------------------------------------------
__global__ void hist_kernel(const int* __restrict__ nout, const int* __restrict__ rel) {
    const int e4 = blockIdx.x * blockDim.x + threadIdx.x;
    if (e4 >= E_EDGES / 4) return;
    const int4 no = reinterpret_cast<const int4*>(nout)[e4];
    const int4 re = reinterpret_cast<const int4*>(rel)[e4];
    atomicAdd(&g_cnt[no.x * R_REL + re.x], 1);
    atomicAdd(&g_cnt[no.y * R_REL + re.y], 1);
    atomicAdd(&g_cnt[no.z * R_REL + re.z], 1);
    atomicAdd(&g_cnt[no.w * R_REL + re.w], 1);
}

// ---------------------------------------------------------------------------
// Scan: per-block exclusive scan into g_off, block sums into g_bsum;
// the LAST block to finish also exclusive-scans g_bsum in place.
// ---------------------------------------------------------------------------
__global__ void scan_kernel() {
    __shared__ int sd[256];
    __shared__ int is_last;
    const int t = threadIdx.x;
    const int base = blockIdx.x * SCAN_BLK + t * 16;
    int v[16], sum = 0;
    #pragma unroll
    for (int j = 0; j < 16; j++) {
        v[j] = sum;
        const int idx = base + j;
        sum += (idx < NR) ? g_cnt[idx] : 0;
    }
    sd[t] = sum;
    __syncthreads();
    #pragma unroll
    for (int d = 1; d < 256; d <<= 1) {
        int val = sd[t];
        if (t >= d) val += sd[t - d];
        __syncthreads();
        sd[t] = val;
        __syncthreads();
    }
    const int excl = sd[t] - sum;
    #pragma unroll
    for (int j = 0; j < 16; j++) {
        const int idx = base + j;
        if (idx < NR) g_off[idx] = excl + v[j];
    }
    if (t == 255) g_bsum[blockIdx.x] = sd[255];

    // last-block tail: scan g_bsum
    __syncthreads();
    if (t == 0) {
        __threadfence();
        is_last = (atomicAdd(&g_scan_ctr, 1) == gridDim.x - 1) ? 1 : 0;
    }
    __syncthreads();
    if (is_last) {
        __shared__ int sb[128];
        if (t < 128) {
            const int orig = (t < NSCAN) ? g_bsum[t] : 0;
            sb[t] = orig;
            __syncwarp();
            // block-level Hillis-Steele over 128 entries (use syncthreads-free
            // path is unsafe across warps; do it with barriers on the 256-thread block)
        }
        __syncthreads();
        #pragma unroll
        for (int d = 1; d < 128; d <<= 1) {
            int val = 0;
            if (t < 128) {
                val = sb[t];
                if (t >= d) val += sb[t - d];
            }
            __syncthreads();
            if (t < 128) sb[t] = val;
            __syncthreads();
        }
        if (t < NSCAN) {
            const int orig = g_bsum[t];
            g_bsum[t] = sb[t] - orig;   // exclusive prefix
        }
    }
}

// ---------------------------------------------------------------------------
// Fill: bump g_off[seg] (local), absolute pos = local + bsum prefix
// ---------------------------------------------------------------------------
__global__ void fill_kernel(const int* __restrict__ nout, const int* __restrict__ rel) {
    const int e = blockIdx.x * blockDim.x + threadIdx.x;
    if (e >= E_EDGES) return;
    const int seg = nout[e] * R_REL + rel[e];
    const int pos = atomicAdd(&g_off[seg], 1) + g_bsum[seg >> 12];
    g_eidx[pos] = e;
}

// ---------------------------------------------------------------------------
// Aggregate: warp per segment; start = g_off[seg]-cnt+bsum (g_off was bumped
// by fill to local_start+cnt). Writes fp16 mean; r==0 warp also copies x row.
// ---------------------------------------------------------------------------
__global__ void aggregate_kernel(const float* __restrict__ x,
                                 const float* __restrict__ ew,
                                 const int* __restrict__ nin) {
    const int seg = (blockIdx.x * blockDim.x + threadIdx.x) >> 5;
    const int lane = threadIdx.x & 31;
    if (seg >= NR) return;

    const int node = seg >> 3;
    const int r = seg & 7;

    if (r == 0) {   // copy x row into g_A cols 1024..1151 (fp16)
        const float4 xv = *reinterpret_cast<const float4*>(x + (size_t)node * D + lane * 4);
        __half2 h0 = __floats2half2_rn(xv.x, xv.y);
        __half2 h1 = __floats2half2_rn(xv.z, xv.w);
        uint2 o;
        o.x = *reinterpret_cast<uint32_t*>(&h0);
        o.y = *reinterpret_cast<uint32_t*>(&h1);
        *reinterpret_cast<uint2*>(g_A + (size_t)node * KTOT + KA + lane * 4) = o;
    }

    const int cnt = g_cnt[seg];
    const int start = g_off[seg] - cnt + g_bsum[seg >> 12];

    float4 acc = make_float4(0.f, 0.f, 0.f, 0.f);
    float den = 0.f;
    int i = 0;
    for (; i + 2 <= cnt; i += 2) {
        const int e0 = g_eidx[start + i];
        const int e1 = g_eidx[start + i + 1];
        const float w0 = ew[e0], w1 = ew[e1];
        const int v0 = nin[e0], v1 = nin[e1];
        const float4 x0 = *reinterpret_cast<const float4*>(x + (size_t)v0 * D + lane * 4);
        const float4 x1 = *reinterpret_cast<const float4*>(x + (size_t)v1 * D + lane * 4);
        acc.x += w0 * x0.x + w1 * x1.x;
        acc.y += w0 * x0.y + w1 * x1.y;
        acc.z += w0 * x0.z + w1 * x1.z;
        acc.w += w0 * x0.w + w1 * x1.w;
        den += w0 + w1;
    }
    if (i < cnt) {
        const int e0 = g_eidx[start + i];
        const float w0 = ew[e0];
        const int v0 = nin[e0];
        const float4 x0 = *reinterpret_cast<const float4*>(x + (size_t)v0 * D + lane * 4);
        acc.x += w0 * x0.x; acc.y += w0 * x0.y;
        acc.z += w0 * x0.z; acc.w += w0 * x0.w;
        den += w0;
    }
    const float s = 1.0f / (den + 1e-10f);
    __half2 h0 = __floats2half2_rn(acc.x * s, acc.y * s);
    __half2 h1 = __floats2half2_rn(acc.z * s, acc.w * s);
    uint2 o;
    o.x = *reinterpret_cast<uint32_t*>(&h0);
    o.y = *reinterpret_cast<uint32_t*>(&h1);
    *reinterpret_cast<uint2*>(g_A + (size_t)node * KTOT + r * 128 + lane * 4) = o;
}

// ---------------------------------------------------------------------------
// FP16 GEMM, persistent single wave (unchanged from round 13):
// out = relu( g_A @ g_BT^T + bias ).  m16n8k16, fp32 accumulate.
// BM=BN=128, BK=32/stage, NSTG=5, 4 stages in flight, 296 blocks, tile counter.
// ---------------------------------------------------------------------------
#define TS_B 80
#define STG_B (128 * TS_B)
#define NSTG 5
#define AS_OFF 0
#define BS_OFF (NSTG * STG_B)
#define BIAS_OFF (2 * NSTG * STG_B)
#define SM_TOTAL (BIAS_OFF + 768)
#define NIT (KTOT / 32)

#define LDSM4(R0, R1, R2, R3, ADDR)                                             \
    asm volatile("ldmatrix.sync.aligned.m8n8.x4.shared.b16 {%0,%1,%2,%3}, [%4];"\
                 : "=r"(R0), "=r"(R1), "=r"(R2), "=r"(R3) : "r"(ADDR))
#define LDSM2(R0, R1, ADDR)                                                     \
    asm volatile("ldmatrix.sync.aligned.m8n8.x2.shared.b16 {%0,%1}, [%2];"      \
                 : "=r"(R0), "=r"(R1) : "r"(ADDR))
#define MMA16(CC, A0, A1, A2, A3, B0, B1)                                       \
    asm volatile(                                                               \
        "mma.sync.aligned.m16n8k16.row.col.f32.f16.f16.f32 "                    \
        "{%0,%1,%2,%3}, {%4,%5,%6,%7}, {%8,%9}, {%0,%1,%2,%3};\n"               \
        : "+f"(CC[0]), "+f"(CC[1]), "+f"(CC[2]), "+f"(CC[3])                    \
        : "r"(A0), "r"(A1), "r"(A2), "r"(A3), "r"(B0), "r"(B1))

__global__ __launch_bounds__(256, 2)
void gemm_fp16(const float* __restrict__ blin, const float* __restrict__ bloop,
               float* __restrict__ out) {
    extern __shared__ char smem[];
    float* bias_s = reinterpret_cast<float*>(smem + BIAS_OFF);
    int* s_tile = reinterpret_cast<int*>(smem + BIAS_OFF + 512);
    const uint32_t smb = smem_u32(smem);

    const int tid  = threadIdx.x;
    if (tid < 128) bias_s[tid] = blin[tid] + bloop[tid];

    const int lane = tid & 31;
    const int wid  = tid >> 5;
    const int g = lane >> 2;
    const int t = lane & 3;
    const int wm = wid >> 2;
    const int wn = wid & 3;

    const int r0c = tid >> 1;
    const int q0  = (tid & 1) * 2;
    const int q1  = q0 + 1;
    const size_t brow_off = (size_t)r0c * KTOT;

    const int lm_row = (lane & 7) + ((lane >> 3) & 1) * 8;
    const int a_base = (wm * 64 + lm_row) * TS_B + ((lane >> 4) & 1) * 16;
    const int lb = lane & 15;
    const int b_base = (wn * 32 + (lb & 7)) * TS_B + ((lb >> 3) & 1) * 16;

    for (;;) {
        __syncthreads();
        if (tid == 0) *s_tile = atomicAdd(&g_tile_ctr, 1);
        __syncthreads();
        const int tile = *s_tile;
        if (tile >= NTILES) break;

        const int n0blk = tile * 128;
        const int grow = n0blk + r0c;
        const int asz = (grow < N_NODES) ? 16 : 0;
        const size_t arow_off = (size_t)min(grow, N_NODES - 1) * KTOT;

#define ISSUE(ST, K0) do {                                                       \
    const uint32_t ab = smb + AS_OFF + (ST) * STG_B + r0c * TS_B;                \
    const uint32_t bb = smb + BS_OFF + (ST) * STG_B + r0c * TS_B;                \
    cp16(ab + q0 * 16, g_A + arow_off + (K0) + q0 * 8, asz);                     \
    cp16(ab + q1 * 16, g_A + arow_off + (K0) + q1 * 8, asz);                     \
    cp16(bb + q0 * 16, g_BT + brow_off + (K0) + q0 * 8, 16);                     \
    cp16(bb + q1 * 16, g_BT + brow_off + (K0) + q1 * 8, 16);                     \
    asm volatile("cp.async.commit_group;" ::: "memory");                         \
} while (0)

        float c[4][4][4];
        #pragma unroll
        for (int mt = 0; mt < 4; mt++)
            #pragma unroll
            for (int nt = 0; nt < 4; nt++)
                #pragma unroll
                for (int q = 0; q < 4; q++) c[mt][nt][q] = 0.f;

        ISSUE(0, 0);
        ISSUE(1, 32);
        ISSUE(2, 64);
        ISSUE(3, 96);

        for (int it = 0; it < NIT; it++) {
            const int st = it % NSTG;
            const int rem = NIT - 1 - it;
            if (rem >= 3)      asm volatile("cp.async.wait_group 3;" ::: "memory");
            else if (rem == 2) asm volatile("cp.async.wait_group 2;" ::: "memory");
            else if (rem == 1) asm volatile("cp.async.wait_group 1;" ::: "memory");
            else               asm volatile("cp.async.wait_group 0;" ::: "memory");
            __syncthreads();
            if (it + 4 < NIT) ISSUE((it + 4) % NSTG, (it + 4) * 32);

            const uint32_t ab = smb + AS_OFF + st * STG_B + a_base;
            const uint32_t bb = smb + BS_OFF + st * STG_B + b_base;
            #pragma unroll
            for (int ks = 0; ks < 2; ks++) {
                uint32_t a[4][4], b[4][2];
                #pragma unroll
                for (int mt = 0; mt < 4; mt++)
                    LDSM4(a[mt][0], a[mt][1], a[mt][2], a[mt][3],
                          ab + mt * 16 * TS_B + ks * 32);
                #pragma unroll
                for (int nt = 0; nt < 4; nt++)
                    LDSM2(b[nt][0], b[nt][1], bb + nt * 8 * TS_B + ks * 32);
                #pragma unroll
                for (int mt = 0; mt < 4; mt++)
                    #pragma unroll
                    for (int nt = 0; nt < 4; nt++)
                        MMA16(c[mt][nt], a[mt][0], a[mt][1], a[mt][2], a[mt][3],
                              b[nt][0], b[nt][1]);
            }
        }

        #pragma unroll
        for (int mt = 0; mt < 4; mt++) {
            const int r0 = n0blk + wm * 64 + mt * 16 + g;
            const int r1 = r0 + 8;
            #pragma unroll
            for (int nt = 0; nt < 4; nt++) {
                const int cn = wn * 32 + nt * 8 + 2 * t;
                const float b0 = bias_s[cn], b1 = bias_s[cn + 1];
                if (r0 < N_NODES) {
                    float2 v;
                    v.x = fmaxf(c[mt][nt][0] + b0, 0.f);
                    v.y = fmaxf(c[mt][nt][1] + b1, 0.f);
                    *reinterpret_cast<float2*>(out + (size_t)r0 * 128 + cn) = v;
                }
                if (r1 < N_NODES) {
                    float2 v;
                    v.x = fmaxf(c[mt][nt][2] + b0, 0.f);
                    v.y = fmaxf(c[mt][nt][3] + b1, 0.f);
                    *reinterpret_cast<float2*>(out + (size_t)r1 * 128 + cn) = v;
                }
            }
        }
    }
}

// ---------------------------------------------------------------------------
// Launch. Inputs: 0:x 1:edge_weight 2:W_lin 3:b_lin 4:W_loop 5:b_loop
//                 6:node_in 7:node_out 8:relation
// ---------------------------------------------------------------------------
extern "C" void kernel_launch(void* const* d_in, const int* in_sizes, int n_in,
                              void* d_out, int out_size) {
    const float* x     = (const float*)d_in[0];
    const float* ew    = (const float*)d_in[1];
    const float* Wlin  = (const float*)d_in[2];
    const float* blin  = (const float*)d_in[3];
    const float* Wloop = (const float*)d_in[4];
    const float* bloop = (const float*)d_in[5];
    const int* nin     = (const int*)d_in[6];
    const int* nout    = (const int*)d_in[7];
    const int* rel     = (const int*)d_in[8];
    float* out         = (float*)d_out;

    cudaFuncSetAttribute(gemm_fp16, cudaFuncAttributeMaxDynamicSharedMemorySize, SM_TOTAL);

    init_kernel<<<(NR + 255) / 256, 256>>>(Wlin, Wloop);
    hist_kernel<<<(E_EDGES / 4 + 255) / 256, 256>>>(nout, rel);
    scan_kernel<<<NSCAN, 256>>>();
    fill_kernel<<<(E_EDGES + 255) / 256, 256>>>(nout, rel);
    aggregate_kernel<<<NR / 8, 256>>>(x, ew, nin);
    gemm_fp16<<<296, 256, SM_TOTAL>>>(blin, bloop, out);
}

// round 17
// speedup vs baseline: 1.5477x; 1.0955x over previous
#include <cuda_runtime.h>
#include <cuda_fp16.h>
#include <cstdint>

#define N_NODES 50000
#define D 128
#define R_REL 8
#define E_EDGES 800000
#define NR (N_NODES * R_REL)   // 400000
#define KTOT 1152              // R*D + D
#define KA 1024                // R*D
#define NTILES 391             // M tiles of 128

#define SCAN_BLK 4096
#define NSCAN ((NR + SCAN_BLK - 1) / SCAN_BLK)   // 98
#define XH2 (N_NODES * D / 2)                    // 3.2M half2 elements

// Scratch (__device__ globals; no allocation allowed)
__device__ __half g_A[(size_t)N_NODES * KTOT];   // [N,1152] fp16 A
__device__ __half g_BT[128 * KTOT];              // [n=128, k=1152] fp16 W^T
__device__ __half g_xh[(size_t)N_NODES * D];     // fp16 copy of x (12.8 MB, L2-resident)
__device__ int g_cnt[NR];
__device__ int g_off[NR];                        // block-local excl scan; fill bumps it
__device__ int g_bsum[NSCAN + 1];                // block sums -> exclusive prefix
__device__ int g_eidx[E_EDGES];
__device__ int g_tile_ctr;                       // persistent-GEMM work counter
__device__ int g_scan_ctr;                       // scan last-block counter

__device__ __forceinline__ uint32_t smem_u32(const void* p) {
    uint32_t a;
    asm("{ .reg .u64 t; cvta.to.shared.u64 t, %1; cvt.u32.u64 %0, t; }" : "=r"(a) : "l"(p));
    return a;
}
__device__ __forceinline__ void cp16(uint32_t dst, const void* src, int sz) {
    asm volatile("cp.async.cg.shared.global [%0], [%1], 16, %2;"
                 :: "r"(dst), "l"(src), "r"(sz) : "memory");
}

// ---------------------------------------------------------------------------
// Init: zero g_cnt + counters, build fp16 W^T, convert x -> g_xh
// ---------------------------------------------------------------------------
__global__ void init_kernel(const float* __restrict__ Wlin, const float* __restrict__ Wloop,
                            const float* __restrict__ x) {
    const int i = blockIdx.x * blockDim.x + threadIdx.x;
    if (i < NR) g_cnt[i] = 0;
    if (i == 0) { g_tile_ctr = 0; g_scan_ctr = 0; }
    if (i < 128 * KTOT) {
        const int n = i / KTOT;
        const int k = i % KTOT;
        const float v = (k < KA) ? Wlin[(size_t)k * 128 + n]
                                 : Wloop[(size_t)(k - KA) * 128 + n];
        g_BT[i] = __float2half_rn(v);
    }
    if (i < XH2) {
        const float2 xv = reinterpret_cast<const float2*>(x)[i];
        __half2 h = __floats2half2_rn(xv.x, xv.y);
        reinterpret_cast<__half2*>(g_xh)[i] = h;
    }
}

// ---------------------------------------------------------------------------
// Histogram: 4 edges per thread, vector loads
// ---------------------------------------------------------------------------
__global__ void hist_kernel(const int* __restrict__ nout, const int* __restrict__ rel) {
    const int e4 = blockIdx.x * blockDim.x + threadIdx.x;
    if (e4 >= E_EDGES / 4) return;
    const int4 no = reinterpret_cast<const int4*>(nout)[e4];
    const int4 re = reinterpret_cast<const int4*>(rel)[e4];
    atomicAdd(&g_cnt[no.x * R_REL + re.x], 1);
    atomicAdd(&g_cnt[no.y * R_REL + re.y], 1);
    atomicAdd(&g_cnt[no.z * R_REL + re.z], 1);
    atomicAdd(&g_cnt[no.w * R_REL + re.w], 1);
}

// ---------------------------------------------------------------------------
// Scan: per-block exclusive scan into g_off, block sums into g_bsum;
// the LAST block to finish also exclusive-scans g_bsum in place.
// ---------------------------------------------------------------------------
__global__ void scan_kernel() {
    __shared__ int sd[256];
    __shared__ int is_last;
    const int t = threadIdx.x;
    const int base = blockIdx.x * SCAN_BLK + t * 16;
    int v[16], sum = 0;
    #pragma unroll
    for (int j = 0; j < 16; j++) {
        v[j] = sum;
        const int idx = base + j;
        sum += (idx < NR) ? g_cnt[idx] : 0;
    }
    sd[t] = sum;
    __syncthreads();
    #pragma unroll
    for (int d = 1; d < 256; d <<= 1) {
        int val = sd[t];
        if (t >= d) val += sd[t - d];
        __syncthreads();
        sd[t] = val;
        __syncthreads();
    }
    const int excl = sd[t] - sum;
    #pragma unroll
    for (int j = 0; j < 16; j++) {
        const int idx = base + j;
        if (idx < NR) g_off[idx] = excl + v[j];
    }
    if (t == 255) g_bsum[blockIdx.x] = sd[255];

    __syncthreads();
    if (t == 0) {
        __threadfence();
        is_last = (atomicAdd(&g_scan_ctr, 1) == gridDim.x - 1) ? 1 : 0;
    }
    __syncthreads();
    if (is_last) {
        __shared__ int sb[128];
        if (t < 128) sb[t] = (t < NSCAN) ? g_bsum[t] : 0;
        __syncthreads();
        #pragma unroll
        for (int d = 1; d < 128; d <<= 1) {
            int val = 0;
            if (t < 128) {
                val = sb[t];
                if (t >= d) val += sb[t - d];
            }
            __syncthreads();
            if (t < 128) sb[t] = val;
            __syncthreads();
        }
        if (t < NSCAN) {
            const int orig = g_bsum[t];
            g_bsum[t] = sb[t] - orig;   // exclusive prefix
        }
    }
}

// ---------------------------------------------------------------------------
// Fill: bump g_off[seg] (local), absolute pos = local + bsum prefix
// ---------------------------------------------------------------------------
__global__ void fill_kernel(const int* __restrict__ nout, const int* __restrict__ rel) {
    const int e = blockIdx.x * blockDim.x + threadIdx.x;
    if (e >= E_EDGES) return;
    const int seg = nout[e] * R_REL + rel[e];
    const int pos = atomicAdd(&g_off[seg], 1) + g_bsum[seg >> 12];
    g_eidx[pos] = e;
}

// ---------------------------------------------------------------------------
// Aggregate: warp per segment; gathers fp16 x rows (half traffic), fp32 acc.
// start = g_off[seg]-cnt+bsum. r==0 warp copies fp16 x row straight across.
// ---------------------------------------------------------------------------
__global__ void aggregate_kernel(const float* __restrict__ ew,
                                 const int* __restrict__ nin) {
    const int seg = (blockIdx.x * blockDim.x + threadIdx.x) >> 5;
    const int lane = threadIdx.x & 31;
    if (seg >= NR) return;

    const int node = seg >> 3;
    const int r = seg & 7;

    if (r == 0) {   // copy fp16 x row into g_A cols 1024..1151 (pure move)
        const uint2 xv = *reinterpret_cast<const uint2*>(g_xh + (size_t)node * D + lane * 4);
        *reinterpret_cast<uint2*>(g_A + (size_t)node * KTOT + KA + lane * 4) = xv;
    }

    const int cnt = g_cnt[seg];
    const int start = g_off[seg] - cnt + g_bsum[seg >> 12];

    float4 acc = make_float4(0.f, 0.f, 0.f, 0.f);
    float den = 0.f;
    int i = 0;
    for (; i + 2 <= cnt; i += 2) {
        const int e0 = g_eidx[start + i];
        const int e1 = g_eidx[start + i + 1];
        const float w0 = ew[e0], w1 = ew[e1];
        const int v0 = nin[e0], v1 = nin[e1];
        const uint2 p0 = *reinterpret_cast<const uint2*>(g_xh + (size_t)v0 * D + lane * 4);
        const uint2 p1 = *reinterpret_cast<const uint2*>(g_xh + (size_t)v1 * D + lane * 4);
        const float2 f00 = __half22float2(*reinterpret_cast<const __half2*>(&p0.x));
        const float2 f01 = __half22float2(*reinterpret_cast<const __half2*>(&p0.y));
        const float2 f10 = __half22float2(*reinterpret_cast<const __half2*>(&p1.x));
        const float2 f11 = __half22float2(*reinterpret_cast<const __half2*>(&p1.y));
        acc.x += w0 * f00.x + w1 * f10.x;
        acc.y += w0 * f00.y + w1 * f10.y;
        acc.z += w0 * f01.x + w1 * f11.x;
        acc.w += w0 * f01.y + w1 * f11.y;
        den += w0 + w1;
    }
    if (i < cnt) {
        const int e0 = g_eidx[start + i];
        const float w0 = ew[e0];
        const int v0 = nin[e0];
        const uint2 p0 = *reinterpret_cast<const uint2*>(g_xh + (size_t)v0 * D + lane * 4);
        const float2 f00 = __half22float2(*reinterpret_cast<const __half2*>(&p0.x));
        const float2 f01 = __half22float2(*reinterpret_cast<const __half2*>(&p0.y));
        acc.x += w0 * f00.x;
        acc.y += w0 * f00.y;
        acc.z += w0 * f01.x;
        acc.w += w0 * f01.y;
        den += w0;
    }
    const float s = 1.0f / (den + 1e-10f);
    __half2 h0 = __floats2half2_rn(acc.x * s, acc.y * s);
    __half2 h1 = __floats2half2_rn(acc.z * s, acc.w * s);
    uint2 o;
    o.x = *reinterpret_cast<uint32_t*>(&h0);
    o.y = *reinterpret_cast<uint32_t*>(&h1);
    *reinterpret_cast<uint2*>(g_A + (size_t)node * KTOT + r * 128 + lane * 4) = o;
}

// ---------------------------------------------------------------------------
// FP16 GEMM, persistent single wave (byte-identical to the 223.2 us kernel):
// out = relu( g_A @ g_BT^T + bias ).  m16n8k16, fp32 accumulate.
// ---------------------------------------------------------------------------
#define TS_B 80
#define STG_B (128 * TS_B)
#define NSTG 5
#define AS_OFF 0
#define BS_OFF (NSTG * STG_B)
#define BIAS_OFF (2 * NSTG * STG_B)
#define SM_TOTAL (BIAS_OFF + 768)
#define NIT (KTOT / 32)

#define LDSM4(R0, R1, R2, R3, ADDR)                                             \
    asm volatile("ldmatrix.sync.aligned.m8n8.x4.shared.b16 {%0,%1,%2,%3}, [%4];"\
                 : "=r"(R0), "=r"(R1), "=r"(R2), "=r"(R3) : "r"(ADDR))
#define LDSM2(R0, R1, ADDR)                                                     \
    asm volatile("ldmatrix.sync.aligned.m8n8.x2.shared.b16 {%0,%1}, [%2];"      \
                 : "=r"(R0), "=r"(R1) : "r"(ADDR))
#define MMA16(CC, A0, A1, A2, A3, B0, B1)                                       \
    asm volatile(                                                               \
        "mma.sync.aligned.m16n8k16.row.col.f32.f16.f16.f32 "                    \
        "{%0,%1,%2,%3}, {%4,%5,%6,%7}, {%8,%9}, {%0,%1,%2,%3};\n"               \
        : "+f"(CC[0]), "+f"(CC[1]), "+f"(CC[2]), "+f"(CC[3])                    \
        : "r"(A0), "r"(A1), "r"(A2), "r"(A3), "r"(B0), "r"(B1))

__global__ __launch_bounds__(256, 2)
void gemm_fp16(const float* __restrict__ blin, const float* __restrict__ bloop,
               float* __restrict__ out) {
    extern __shared__ char smem[];
    float* bias_s = reinterpret_cast<float*>(smem + BIAS_OFF);
    int* s_tile = reinterpret_cast<int*>(smem + BIAS_OFF + 512);
    const uint32_t smb = smem_u32(smem);

    const int tid  = threadIdx.x;
    if (tid < 128) bias_s[tid] = blin[tid] + bloop[tid];

    const int lane = tid & 31;
    const int wid  = tid >> 5;
    const int g = lane >> 2;
    const int t = lane & 3;
    const int wm = wid >> 2;
    const int wn = wid & 3;

    const int r0c = tid >> 1;
    const int q0  = (tid & 1) * 2;
    const int q1  = q0 + 1;
    const size_t brow_off = (size_t)r0c * KTOT;

    const int lm_row = (lane & 7) + ((lane >> 3) & 1) * 8;
    const int a_base = (wm * 64 + lm_row) * TS_B + ((lane >> 4) & 1) * 16;
    const int lb = lane & 15;
    const int b_base = (wn * 32 + (lb & 7)) * TS_B + ((lb >> 3) & 1) * 16;

    for (;;) {
        __syncthreads();
        if (tid == 0) *s_tile = atomicAdd(&g_tile_ctr, 1);
        __syncthreads();
        const int tile = *s_tile;
        if (tile >= NTILES) break;

        const int n0blk = tile * 128;
        const int grow = n0blk + r0c;
        const int asz = (grow < N_NODES) ? 16 : 0;
        const size_t arow_off = (size_t)min(grow, N_NODES - 1) * KTOT;

#define ISSUE(ST, K0) do {                                                       \
    const uint32_t ab = smb + AS_OFF + (ST) * STG_B + r0c * TS_B;                \
    const uint32_t bb = smb + BS_OFF + (ST) * STG_B + r0c * TS_B;                \
    cp16(ab + q0 * 16, g_A + arow_off + (K0) + q0 * 8, asz);                     \
    cp16(ab + q1 * 16, g_A + arow_off + (K0) + q1 * 8, asz);                     \
    cp16(bb + q0 * 16, g_BT + brow_off + (K0) + q0 * 8, 16);                     \
    cp16(bb + q1 * 16, g_BT + brow_off + (K0) + q1 * 8, 16);                     \
    asm volatile("cp.async.commit_group;" ::: "memory");                         \
} while (0)

        float c[4][4][4];
        #pragma unroll
        for (int mt = 0; mt < 4; mt++)
            #pragma unroll
            for (int nt = 0; nt < 4; nt++)
                #pragma unroll
                for (int q = 0; q < 4; q++) c[mt][nt][q] = 0.f;

        ISSUE(0, 0);
        ISSUE(1, 32);
        ISSUE(2, 64);
        ISSUE(3, 96);

        for (int it = 0; it < NIT; it++) {
            const int st = it % NSTG;
            const int rem = NIT - 1 - it;
            if (rem >= 3)      asm volatile("cp.async.wait_group 3;" ::: "memory");
            else if (rem == 2) asm volatile("cp.async.wait_group 2;" ::: "memory");
            else if (rem == 1) asm volatile("cp.async.wait_group 1;" ::: "memory");
            else               asm volatile("cp.async.wait_group 0;" ::: "memory");
            __syncthreads();
            if (it + 4 < NIT) ISSUE((it + 4) % NSTG, (it + 4) * 32);

            const uint32_t ab = smb + AS_OFF + st * STG_B + a_base;
            const uint32_t bb = smb + BS_OFF + st * STG_B + b_base;
            #pragma unroll
            for (int ks = 0; ks < 2; ks++) {
                uint32_t a[4][4], b[4][2];
                #pragma unroll
                for (int mt = 0; mt < 4; mt++)
                    LDSM4(a[mt][0], a[mt][1], a[mt][2], a[mt][3],
                          ab + mt * 16 * TS_B + ks * 32);
                #pragma unroll
                for (int nt = 0; nt < 4; nt++)
                    LDSM2(b[nt][0], b[nt][1], bb + nt * 8 * TS_B + ks * 32);
                #pragma unroll
                for (int mt = 0; mt < 4; mt++)
                    #pragma unroll
                    for (int nt = 0; nt < 4; nt++)
                        MMA16(c[mt][nt], a[mt][0], a[mt][1], a[mt][2], a[mt][3],
                              b[nt][0], b[nt][1]);
            }
        }

        #pragma unroll
        for (int mt = 0; mt < 4; mt++) {
            const int r0 = n0blk + wm * 64 + mt * 16 + g;
            const int r1 = r0 + 8;
            #pragma unroll
            for (int nt = 0; nt < 4; nt++) {
                const int cn = wn * 32 + nt * 8 + 2 * t;
                const float b0 = bias_s[cn], b1 = bias_s[cn + 1];
                if (r0 < N_NODES) {
                    float2 v;
                    v.x = fmaxf(c[mt][nt][0] + b0, 0.f);
                    v.y = fmaxf(c[mt][nt][1] + b1, 0.f);
                    *reinterpret_cast<float2*>(out + (size_t)r0 * 128 + cn) = v;
                }
                if (r1 < N_NODES) {
                    float2 v;
                    v.x = fmaxf(c[mt][nt][2] + b0, 0.f);
                    v.y = fmaxf(c[mt][nt][3] + b1, 0.f);
                    *reinterpret_cast<float2*>(out + (size_t)r1 * 128 + cn) = v;
                }
            }
        }
    }
}

// ---------------------------------------------------------------------------
// Launch. Inputs: 0:x 1:edge_weight 2:W_lin 3:b_lin 4:W_loop 5:b_loop
//                 6:node_in 7:node_out 8:relation
// ---------------------------------------------------------------------------
extern "C" void kernel_launch(void* const* d_in, const int* in_sizes, int n_in,
                              void* d_out, int out_size) {
    const float* x     = (const float*)d_in[0];
    const float* ew    = (const float*)d_in[1];
    const float* Wlin  = (const float*)d_in[2];
    const float* blin  = (const float*)d_in[3];
    const float* Wloop = (const float*)d_in[4];
    const float* bloop = (const float*)d_in[5];
    const int* nin     = (const int*)d_in[6];
    const int* nout    = (const int*)d_in[7];
    const int* rel     = (const int*)d_in[8];
    float* out         = (float*)d_out;

    cudaFuncSetAttribute(gemm_fp16, cudaFuncAttributeMaxDynamicSharedMemorySize, SM_TOTAL);

    init_kernel<<<(XH2 + 255) / 256, 256>>>(Wlin, Wloop, x);
    hist_kernel<<<(E_EDGES / 4 + 255) / 256, 256>>>(nout, rel);
    scan_kernel<<<NSCAN, 256>>>();
    fill_kernel<<<(E_EDGES + 255) / 256, 256>>>(nout, rel);
    aggregate_kernel<<<NR / 8, 256>>>(ew, nin);
    gemm_fp16<<<296, 256, SM_TOTAL>>>(blin, bloop, out);
}